// round 12
// baseline (speedup 1.0000x reference)
#include <cuda_runtime.h>
#include <cstdint>
#include <math.h>

// Problem dims (fixed by setup_inputs)
#define TT 50
#define BB 256
#define AA 64
#define SS 256
#define HH 1024
#define OO 1024
#define NCTA 296
#define B3H (BB * 3 * HH)
#define BH  (BB * HH)
#define B2S (BB * 2 * SS)

// ---------------- device scratch (static allocation only) ----------------
__device__ float g_noise[2 * TT * BB * SS];        // 26 MB
__device__ float g_qobs[TT * BB * HH];             // 52 MB; reused as p1_all post-scan
__device__ float g_phall[TT * BB * 2 * SS];        // 26 MB (ph_all post-scan)
__device__ float g_belief[BH];
__device__ float g_state[BB * SS];
__device__ float g_h1[BH];
__device__ float g_hg4[4 * B3H];                   // hg K-split partials
__device__ float g_xg4[4 * B3H];
__device__ float g_q18[8 * BH];
__device__ float g_qh8[8 * B2S];
__device__ unsigned g_arrive;
__device__ unsigned g_release;
__device__ unsigned g_ticket;

// ---------------- helpers ----------------
__device__ __forceinline__ void unpack2(unsigned long long v, float& x, float& y) {
    asm("mov.b64 {%0, %1}, %2;" : "=f"(x), "=f"(y) : "l"(v));
}
__device__ __forceinline__ unsigned long long ffma2(unsigned long long a,
                                                    unsigned long long b,
                                                    unsigned long long c) {
    unsigned long long d;
    asm("fma.rn.f32x2 %0, %1, %2, %3;" : "=l"(d) : "l"(a), "l"(b), "l"(c));
    return d;
}
__device__ __forceinline__ float sigmoidf_(float x) { return 1.0f / (1.0f + expf(-x)); }
__device__ __forceinline__ float softplusf_(float x) {
    return fmaxf(x, 0.0f) + log1pf(expf(-fabsf(x)));
}
__device__ __forceinline__ unsigned ld_acquire(unsigned* p) {
    unsigned v;
    asm volatile("ld.acquire.gpu.u32 %0, [%1];" : "=r"(v) : "l"(p));
    return v;
}

// ---------------- grid-wide barrier + ticket reset ----------------
__device__ __forceinline__ void grid_bar(unsigned gen) {
    __syncthreads();
    if (threadIdx.x == 0) {
        __threadfence();
        if (atomicAdd(&g_arrive, 1) == gridDim.x - 1) {
            g_arrive = 0;
            g_ticket = 0;                      // fresh tickets for next phase
            __threadfence();
            atomicExch(&g_release, gen);
        } else {
            while (ld_acquire(&g_release) < gen) __nanosleep(32);
        }
    }
    __syncthreads();
}

// ---------------- JAX threefry2x32 noise (key = (0,42)) ----------------
__device__ __forceinline__ uint32_t rotl32(uint32_t x, int r) {
    return (x << r) | (x >> (32 - r));
}
__device__ __forceinline__ float normal_from_bits(uint32_t bits) {
    uint32_t fb = (bits >> 9) | 0x3f800000u;
    float f = __uint_as_float(fb) - 1.0f;
    const float lo = -0.99999994f;
    float u = f * 2.0f + lo;
    u = fmaxf(lo, u);
    float w = -log1pf(-u * u);
    float p;
    if (w < 5.0f) {
        w -= 2.5f;
        p = 2.81022636e-08f;
        p = fmaf(p, w, 3.43273939e-07f);
        p = fmaf(p, w, -3.5233877e-06f);
        p = fmaf(p, w, -4.39150654e-06f);
        p = fmaf(p, w, 0.00021858087f);
        p = fmaf(p, w, -0.00125372503f);
        p = fmaf(p, w, -0.00417768164f);
        p = fmaf(p, w, 0.246640727f);
        p = fmaf(p, w, 1.50140941f);
    } else {
        w = sqrtf(w) - 3.0f;
        p = -0.000200214257f;
        p = fmaf(p, w, 0.000100950558f);
        p = fmaf(p, w, 0.00134934322f);
        p = fmaf(p, w, -0.00367342844f);
        p = fmaf(p, w, 0.00573950773f);
        p = fmaf(p, w, -0.0076224613f);
        p = fmaf(p, w, 0.00943887047f);
        p = fmaf(p, w, 1.00167406f);
        p = fmaf(p, w, 2.83297682f);
    }
    return 1.41421356f * (p * u);
}

__global__ void noise_kernel() {
    const int total = 2 * TT * BB * SS;
    int i = blockIdx.x * blockDim.x + threadIdx.x;
    if (i >= total) return;
    const uint32_t k0 = 0u, k1 = 42u;
    const uint32_t k2 = k0 ^ k1 ^ 0x1BD11BDAu;
    uint32_t x0 = 0u;
    uint32_t x1 = (uint32_t)i;
    x0 += k0; x1 += k1;
#define RND(r) { x0 += x1; x1 = rotl32(x1, r); x1 ^= x0; }
    RND(13) RND(15) RND(26) RND(6)   x0 += k1; x1 += k2 + 1u;
    RND(17) RND(29) RND(16) RND(24)  x0 += k2; x1 += k0 + 2u;
    RND(13) RND(15) RND(26) RND(6)   x0 += k0; x1 += k1 + 3u;
    RND(17) RND(29) RND(16) RND(24)  x0 += k1; x1 += k2 + 4u;
    RND(13) RND(15) RND(26) RND(6)   x0 += k2; x1 += k0 + 5u;
#undef RND
    g_noise[i] = normal_from_bits(x0 ^ x1);
}

__global__ void init_kernel(const float* __restrict__ prev_state,
                            const float* __restrict__ prev_belief) {
    int i = blockIdx.x * blockDim.x + threadIdx.x;
    if (i == 0) { g_arrive = 0; g_release = 0; g_ticket = 0; }
    if (i < BB * SS) g_state[i] = prev_state[i];
    if (i < BB * HH) g_belief[i] = prev_belief[i];
}

// ---------------- generic GEMM tile (FFMA2, 64x128, double-buffered) -------
// A staged into smem PRE-DUPLICATED as (a,a) float2 pairs -> inner loop reads
// FFMA2-ready 64-bit operands directly (no packing MOVs).
struct TileOp {
    const float* A0; int lda; int K0;
    int nSum; size_t sumStride;
    const float* Aextra;            // optional extra matrix summand (same lda)
    const float* Acb;               // optional per-k bias on A
    int reluA;
    const float* rowscale;
    const float* A1; int K1;        // optional concat block, row stride K1
    const float* W;                 // [K, N] row-major (pre-offset for K-split)
    const float* bias;              // [N] or null
    float* C; int N;
    int relu;
};

#define AS2W 132                    // 128 duplicated floats + 4 pad

__device__ void gemm_tile(const TileOp op, int m0, int n0,
                          float As2[2][16][AS2W], float Ws[2][16][128]) {
    __syncthreads();                 // smem reuse guard
    const int t = threadIdx.x;
    const int tx = t & 15, ty = t >> 4;
    const int K = op.K0 + op.K1;
    const int nchunks = K >> 4;

    const int am = t >> 2;
    const int ak = (t & 3) << 2;
    const int gm = m0 + am;
    const float rs = op.rowscale ? op.rowscale[gm] : 1.0f;
    const int wk0 = t >> 5;
    const int wn0 = (t & 31) << 2;
    const int wk1 = (t + 256) >> 5;

    unsigned long long acc[4][4];
#pragma unroll
    for (int i = 0; i < 4; ++i)
#pragma unroll
        for (int j = 0; j < 4; ++j) acc[i][j] = 0ull;

    float4 aReg, wReg0, wReg1;

    auto load_regs = [&](int c) {
        int gk = (c << 4) + ak;
        if (gk < op.K0) {
            const float* a = op.A0 + (size_t)gm * op.lda + gk;
            float4 v = *(const float4*)a;
            for (int j = 1; j < op.nSum; ++j) {
                const float4 e = *(const float4*)(a + (size_t)j * op.sumStride);
                v.x += e.x; v.y += e.y; v.z += e.z; v.w += e.w;
            }
            if (op.Aextra) {
                const float4 e = *(const float4*)(op.Aextra + (size_t)gm * op.lda + gk);
                v.x += e.x; v.y += e.y; v.z += e.z; v.w += e.w;
            }
            if (op.Acb) {
                const float4 e = *(const float4*)(op.Acb + gk);
                v.x += e.x; v.y += e.y; v.z += e.z; v.w += e.w;
            }
            if (op.reluA) {
                v.x = fmaxf(v.x, 0.0f); v.y = fmaxf(v.y, 0.0f);
                v.z = fmaxf(v.z, 0.0f); v.w = fmaxf(v.w, 0.0f);
            }
            v.x *= rs; v.y *= rs; v.z *= rs; v.w *= rs;
            aReg = v;
        } else {
            aReg = *(const float4*)(op.A1 + (size_t)gm * op.K1 + (gk - op.K0));
        }
        const float* wbase = op.W + (size_t)(c << 4) * op.N + n0;
        wReg0 = *(const float4*)(wbase + (size_t)wk0 * op.N + wn0);
        wReg1 = *(const float4*)(wbase + (size_t)wk1 * op.N + wn0);
    };
    auto sts = [&](int b) {
        const int m2 = am << 1;
        *(float2*)&As2[b][ak + 0][m2] = make_float2(aReg.x, aReg.x);
        *(float2*)&As2[b][ak + 1][m2] = make_float2(aReg.y, aReg.y);
        *(float2*)&As2[b][ak + 2][m2] = make_float2(aReg.z, aReg.z);
        *(float2*)&As2[b][ak + 3][m2] = make_float2(aReg.w, aReg.w);
        *(float4*)&Ws[b][wk0][wn0] = wReg0;
        *(float4*)&Ws[b][wk1][wn0] = wReg1;
    };

    load_regs(0);
    sts(0);
    __syncthreads();

    int buf = 0;
    for (int c = 0; c < nchunks; ++c) {
        const bool has_next = (c + 1 < nchunks);
        if (has_next) load_regs(c + 1);
#pragma unroll
        for (int kk = 0; kk < 16; ++kk) {
            // A operands pre-duplicated: 2x LDS.128 (broadcast), no MOVs
            const unsigned long long* ar =
                (const unsigned long long*)&As2[buf][kk][ty << 3];
            unsigned long long ap0 = ar[0], ap1 = ar[1];
            unsigned long long ap2 = ar[2], ap3 = ar[3];
            const unsigned long long* wr =
                (const unsigned long long*)(&Ws[buf][kk][tx << 3]);
            unsigned long long w0 = wr[0], w1 = wr[1], w2 = wr[2], w3 = wr[3];
            acc[0][0] = ffma2(ap0, w0, acc[0][0]);
            acc[0][1] = ffma2(ap0, w1, acc[0][1]);
            acc[0][2] = ffma2(ap0, w2, acc[0][2]);
            acc[0][3] = ffma2(ap0, w3, acc[0][3]);
            acc[1][0] = ffma2(ap1, w0, acc[1][0]);
            acc[1][1] = ffma2(ap1, w1, acc[1][1]);
            acc[1][2] = ffma2(ap1, w2, acc[1][2]);
            acc[1][3] = ffma2(ap1, w3, acc[1][3]);
            acc[2][0] = ffma2(ap2, w0, acc[2][0]);
            acc[2][1] = ffma2(ap2, w1, acc[2][1]);
            acc[2][2] = ffma2(ap2, w2, acc[2][2]);
            acc[2][3] = ffma2(ap2, w3, acc[2][3]);
            acc[3][0] = ffma2(ap3, w0, acc[3][0]);
            acc[3][1] = ffma2(ap3, w1, acc[3][1]);
            acc[3][2] = ffma2(ap3, w2, acc[3][2]);
            acc[3][3] = ffma2(ap3, w3, acc[3][3]);
        }
        if (has_next) {
            sts(buf ^ 1);
            __syncthreads();
            buf ^= 1;
        }
    }

    const int nb = n0 + (tx << 3);
    const int mb = m0 + (ty << 2);
    float bs[8];
#pragma unroll
    for (int c = 0; c < 8; ++c) bs[c] = op.bias ? op.bias[nb + c] : 0.0f;
#pragma unroll
    for (int i = 0; i < 4; ++i) {
        float o[8];
#pragma unroll
        for (int j = 0; j < 4; ++j) unpack2(acc[i][j], o[2 * j], o[2 * j + 1]);
#pragma unroll
        for (int c = 0; c < 8; ++c) {
            o[c] += bs[c];
            if (op.relu) o[c] = fmaxf(o[c], 0.0f);
        }
        float4* dst = (float4*)(op.C + (size_t)(mb + i) * op.N + nb);
        dst[0] = make_float4(o[0], o[1], o[2], o[3]);
        dst[1] = make_float4(o[4], o[5], o[6], o[7]);
    }
}

// Static-grid tile launcher (pre/post big GEMMs)
__global__ __launch_bounds__(256) void gemm_big(TileOp op) {
    __shared__ __align__(16) float As2[2][16][AS2W];
    __shared__ __align__(16) float Ws[2][16][128];
    gemm_tile(op, blockIdx.y * 64, blockIdx.x * 128, As2, Ws);
}

// ---------------- persistent scan kernel (posterior critical path) ---------
__global__ __launch_bounds__(256, 2) void rssm_kernel(
    const float* __restrict__ actions,
    const float* __restrict__ nonterminals,
    const float* __restrict__ W_sa, const float* __restrict__ b_sa,
    const float* __restrict__ W_x,  const float* __restrict__ W_h,
    const float* __restrict__ b_x,  const float* __restrict__ b_h,
    const float* __restrict__ W_bq, const float* __restrict__ b_bq,
    const float* __restrict__ W_sq, const float* __restrict__ b_sq,
    float* __restrict__ out, int full)
{
    __shared__ __align__(16) float As2[2][16][AS2W];
    __shared__ __align__(16) float Ws[2][16][128];
    __shared__ unsigned sPiece;
    const int bid = blockIdx.x;
    const int stride = gridDim.x;
    const int tid = threadIdx.x;
    unsigned gen = 0;

    const size_t O_BEL  = 0;
    const size_t O_POST = (size_t)TT * BB * HH + 3 * (size_t)TT * BB * SS;
    const size_t O_QM   = O_POST + (size_t)TT * BB * SS;
    const size_t O_QS   = O_QM   + (size_t)TT * BB * SS;

    auto grab = [&]() -> unsigned {
        __syncthreads();
        if (tid == 0) sPiece = atomicAdd(&g_ticket, 1);
        __syncthreads();
        return sPiece;
    };

    for (int t = 0; t < TT; ++t) {
        const float* a_t  = actions + (size_t)t * BB * AA;
        const float* nt_t = nonterminals + (size_t)t * BB;
        const float* qo_t = g_qobs + (size_t)t * BB * HH;

        // Phase A: h1 (32 pieces) + hg K-split4 (384 pieces)
        for (unsigned p = grab(); p < 416; p = grab()) {
            if (p < 32) {
                TileOp op{g_state, SS, SS, 1, 0, nullptr, nullptr, 0, nt_t,
                          a_t, AA, W_sa, b_sa, g_h1, HH, 1};
                gemm_tile(op, (p & 3) * 64, (p >> 2) * 128, As2, Ws);
            } else {
                unsigned q = p - 32;
                int tile = q >> 2, ks = q & 3;
                TileOp op{g_belief + ks * 256, HH, 256, 1, 0, nullptr, nullptr, 0,
                          nullptr, nullptr, 0, W_h + (size_t)ks * 256 * 3 * HH,
                          nullptr, g_hg4 + (size_t)ks * B3H, 3 * HH, 0};
                gemm_tile(op, (tile & 3) * 64, (tile >> 2) * 128, As2, Ws);
            }
        }
        grid_bar(++gen);

        // Phase B: xg K-split4 (384 pieces)
        for (unsigned p = grab(); p < 384; p = grab()) {
            int tile = p >> 2, ks = p & 3;
            TileOp op{g_h1 + ks * 256, HH, 256, 1, 0, nullptr, nullptr, 0,
                      nullptr, nullptr, 0, W_x + (size_t)ks * 256 * 3 * HH,
                      nullptr, g_xg4 + (size_t)ks * B3H, 3 * HH, 0};
            gemm_tile(op, (tile & 3) * 64, (tile >> 2) * 128, As2, Ws);
        }
        grid_bar(++gen);

        // Phase C: GRU elementwise (sums partials) -> belief (+ output)
        {
            float* ob = out + O_BEL + (size_t)t * BB * HH;
            for (int idx = bid * 256 + tid; idx < BB * HH; idx += stride * 256) {
                int b = idx >> 10, j = idx & 1023;
                size_t base = (size_t)b * 3072 + j;
                float xz = b_x[j], xr = b_x[1024 + j], xh = b_x[2048 + j];
                float hz = b_h[j], hr = b_h[1024 + j], hh = b_h[2048 + j];
#pragma unroll
                for (int jp = 0; jp < 4; ++jp) {
                    const float* xp = g_xg4 + (size_t)jp * B3H + base;
                    const float* hp = g_hg4 + (size_t)jp * B3H + base;
                    xz += xp[0]; xr += xp[1024]; xh += xp[2048];
                    hz += hp[0]; hr += hp[1024]; hh += hp[2048];
                }
                float z = sigmoidf_(xz + hz);
                float r = sigmoidf_(xr + hr);
                float cand = tanhf(xh + r * hh);
                float bo = g_belief[idx];
                float bn = z * bo + (1.0f - z) * cand;
                g_belief[idx] = bn;
                ob[idx] = bn;
            }
        }
        grid_bar(++gen);

        // Phase D: q1 = bel @ W_bq[:H]  K-split8 (256 pieces, partials)
        for (unsigned p = grab(); p < 256; p = grab()) {
            int tile = p >> 3, ks = p & 7;
            TileOp op{g_belief + ks * 128, HH, 128, 1, 0, nullptr, nullptr, 0,
                      nullptr, nullptr, 0, W_bq + (size_t)ks * 128 * HH,
                      nullptr, g_q18 + (size_t)ks * BH, HH, 0};
            gemm_tile(op, (tile & 3) * 64, (tile >> 2) * 128, As2, Ws);
        }
        grid_bar(++gen);

        // Phase E: qh = relu(sum q1 + qobs + b_bq) @ W_sq  K-split8 (128 pieces)
        for (unsigned p = grab(); p < 128; p = grab()) {
            int tile = p >> 3, ks = p & 7;
            TileOp op{g_q18 + ks * 128, HH, 128, 8, (size_t)BH, qo_t + ks * 128,
                      b_bq + ks * 128, 1, nullptr, nullptr, 0,
                      W_sq + (size_t)ks * 128 * 2 * SS,
                      nullptr, g_qh8 + (size_t)ks * B2S, 2 * SS, 0};
            gemm_tile(op, (tile & 3) * 64, (tile >> 2) * 128, As2, Ws);
        }
        grid_bar(++gen);

        // Phase F: posterior heads (sums qh partials) -> outputs + next state
        {
            const float* nQ = g_noise + (size_t)(TT + t) * BB * SS;
            for (int idx = bid * 256 + tid; idx < BB * SS; idx += stride * 256) {
                int b = idx >> 8, s = idx & 255;
                float qm = b_sq[s], qsr = b_sq[256 + s];
#pragma unroll
                for (int jp = 0; jp < 8; ++jp) {
                    const float* qp = g_qh8 + (size_t)jp * B2S + b * 512 + s;
                    qm += qp[0]; qsr += qp[256];
                }
                float qs = softplusf_(qsr) + 0.1f;
                float po = qm + qs * nQ[idx];
                if (full) {
                    size_t o = (size_t)t * BB * SS + idx;
                    out[O_QM + o] = qm; out[O_QS + o] = qs; out[O_POST + o] = po;
                }
                g_state[idx] = po;
            }
        }
        grid_bar(++gen);
    }
}

// ---------------- prior heads elementwise (post-pass) ----------------
__global__ void prior_heads_kernel(float* __restrict__ out, int full) {
    const size_t O_PRI = (size_t)TT * BB * HH;
    const size_t O_PM  = O_PRI + (size_t)TT * BB * SS;
    const size_t O_PS  = O_PM  + (size_t)TT * BB * SS;
    int idx = blockIdx.x * blockDim.x + threadIdx.x;   // over T*B*S
    if (idx >= TT * BB * SS) return;
    int r = idx >> 8, s = idx & 255;
    float pm = g_phall[(size_t)r * 512 + s];
    float ps = softplusf_(g_phall[(size_t)r * 512 + 256 + s]) + 0.1f;
    float pr = pm + ps * g_noise[idx];
    if (full) { out[O_PM + idx] = pm; out[O_PS + idx] = ps; out[O_PRI + idx] = pr; }
}

// ---------------- launch ----------------
extern "C" void kernel_launch(void* const* d_in, const int* in_sizes, int n_in,
                              void* d_out, int out_size) {
    const float* actions      = (const float*)d_in[0];
    const float* prev_state   = (const float*)d_in[1];
    const float* prev_belief  = (const float*)d_in[2];
    const float* observations = (const float*)d_in[3];
    const float* nonterminals = (const float*)d_in[4];
    const float* W_sa = (const float*)d_in[5];
    const float* b_sa = (const float*)d_in[6];
    const float* W_x  = (const float*)d_in[7];
    const float* W_h  = (const float*)d_in[8];
    const float* b_x  = (const float*)d_in[9];
    const float* b_h  = (const float*)d_in[10];
    const float* W_bp = (const float*)d_in[11];
    const float* b_bp = (const float*)d_in[12];
    const float* W_sp = (const float*)d_in[13];
    const float* b_sp = (const float*)d_in[14];
    const float* W_bq = (const float*)d_in[15];
    const float* b_bq = (const float*)d_in[16];
    const float* W_sq = (const float*)d_in[17];
    const float* b_sq = (const float*)d_in[18];
    float* out = (float*)d_out;

    const size_t FULL = (size_t)TT * BB * (HH + 6 * SS);
    const int full = (size_t)out_size >= FULL;

    float *qobs, *phall;
    cudaGetSymbolAddress((void**)&qobs, g_qobs);
    cudaGetSymbolAddress((void**)&phall, g_phall);

    noise_kernel<<<(2 * TT * BB * SS + 255) / 256, 256>>>();
    init_kernel<<<(BB * HH + 255) / 256, 256>>>(prev_state, prev_belief);

    // Pre: qobs[t] = obs[t] @ W_bq[H:, :]   ([12800,1024] x [1024,1024])
    {
        TileOp op{observations, OO, OO, 1, 0, nullptr, nullptr, 0, nullptr,
                  nullptr, 0, W_bq + (size_t)HH * HH, nullptr, qobs, HH, 0};
        gemm_big<<<dim3(HH / 128, (TT * BB) / 64), 256>>>(op);
    }

    // Scan (posterior critical path only)
    rssm_kernel<<<NCTA, 256>>>(actions, nonterminals,
                               W_sa, b_sa, W_x, W_h, b_x, b_h,
                               W_bq, b_bq, W_sq, b_sq, out, full);

    // Post: prior branch batched over all T
    // p1_all = relu(belief_all @ W_bp + b_bp)   (reuses g_qobs as scratch)
    {
        TileOp op{out /*O_BEL*/, HH, HH, 1, 0, nullptr, nullptr, 0, nullptr,
                  nullptr, 0, W_bp, b_bp, qobs, HH, 1};
        gemm_big<<<dim3(HH / 128, (TT * BB) / 64), 256>>>(op);
    }
    // ph_all = p1_all @ W_sp + b_sp
    {
        TileOp op{qobs, HH, HH, 1, 0, nullptr, nullptr, 0, nullptr,
                  nullptr, 0, W_sp, b_sp, phall, 2 * SS, 0};
        gemm_big<<<dim3(2 * SS / 128, (TT * BB) / 64), 256>>>(op);
    }
    prior_heads_kernel<<<(TT * BB * SS + 255) / 256, 256>>>(out, full);
}

// round 13
// speedup vs baseline: 1.0811x; 1.0811x over previous
#include <cuda_runtime.h>
#include <cstdint>
#include <math.h>

// Problem dims (fixed by setup_inputs)
#define TT 50
#define BB 256
#define AA 64
#define SS 256
#define HH 1024
#define OO 1024
#define NCTA 296
#define B3H (BB * 3 * HH)
#define BH  (BB * HH)
#define B2S (BB * 2 * SS)

// ---------------- device scratch (static allocation only) ----------------
__device__ float g_noise[2 * TT * BB * SS];        // 26 MB
__device__ float g_qobs[TT * BB * HH];             // 52 MB; reused as p1_all post-scan
__device__ float g_phall[TT * BB * 2 * SS];        // 26 MB (ph_all post-scan)
__device__ float g_belief[BH];
__device__ float g_state[BB * SS];
__device__ float g_h1[BH];
__device__ float g_hg4[4 * B3H];                   // hg K-split partials
__device__ float g_xg4[4 * B3H];
__device__ float g_q18[8 * BH];
__device__ float g_qh8[8 * B2S];
__device__ unsigned g_arrive;
__device__ unsigned g_release;
__device__ unsigned g_ticket;

// ---------------- helpers ----------------
__device__ __forceinline__ unsigned long long pack2(float x, float y) {
    unsigned long long r;
    asm("mov.b64 %0, {%1, %2};" : "=l"(r) : "f"(x), "f"(y));
    return r;
}
__device__ __forceinline__ void unpack2(unsigned long long v, float& x, float& y) {
    asm("mov.b64 {%0, %1}, %2;" : "=f"(x), "=f"(y) : "l"(v));
}
__device__ __forceinline__ unsigned long long ffma2(unsigned long long a,
                                                    unsigned long long b,
                                                    unsigned long long c) {
    unsigned long long d;
    asm("fma.rn.f32x2 %0, %1, %2, %3;" : "=l"(d) : "l"(a), "l"(b), "l"(c));
    return d;
}
__device__ __forceinline__ float sigmoidf_(float x) { return 1.0f / (1.0f + expf(-x)); }
__device__ __forceinline__ float softplusf_(float x) {
    return fmaxf(x, 0.0f) + log1pf(expf(-fabsf(x)));
}
__device__ __forceinline__ unsigned ld_acquire(unsigned* p) {
    unsigned v;
    asm volatile("ld.acquire.gpu.u32 %0, [%1];" : "=r"(v) : "l"(p));
    return v;
}

// ---------------- grid-wide barrier + ticket reset ----------------
__device__ __forceinline__ void grid_bar(unsigned gen) {
    __syncthreads();
    if (threadIdx.x == 0) {
        __threadfence();
        if (atomicAdd(&g_arrive, 1) == gridDim.x - 1) {
            g_arrive = 0;
            g_ticket = 0;                      // fresh tickets for next phase
            __threadfence();
            atomicExch(&g_release, gen);
        } else {
            while (ld_acquire(&g_release) < gen) __nanosleep(32);
        }
    }
    __syncthreads();
}

// ---------------- JAX threefry2x32 noise (key = (0,42)) ----------------
__device__ __forceinline__ uint32_t rotl32(uint32_t x, int r) {
    return (x << r) | (x >> (32 - r));
}
__device__ __forceinline__ float normal_from_bits(uint32_t bits) {
    uint32_t fb = (bits >> 9) | 0x3f800000u;
    float f = __uint_as_float(fb) - 1.0f;
    const float lo = -0.99999994f;
    float u = f * 2.0f + lo;
    u = fmaxf(lo, u);
    float w = -log1pf(-u * u);
    float p;
    if (w < 5.0f) {
        w -= 2.5f;
        p = 2.81022636e-08f;
        p = fmaf(p, w, 3.43273939e-07f);
        p = fmaf(p, w, -3.5233877e-06f);
        p = fmaf(p, w, -4.39150654e-06f);
        p = fmaf(p, w, 0.00021858087f);
        p = fmaf(p, w, -0.00125372503f);
        p = fmaf(p, w, -0.00417768164f);
        p = fmaf(p, w, 0.246640727f);
        p = fmaf(p, w, 1.50140941f);
    } else {
        w = sqrtf(w) - 3.0f;
        p = -0.000200214257f;
        p = fmaf(p, w, 0.000100950558f);
        p = fmaf(p, w, 0.00134934322f);
        p = fmaf(p, w, -0.00367342844f);
        p = fmaf(p, w, 0.00573950773f);
        p = fmaf(p, w, -0.0076224613f);
        p = fmaf(p, w, 0.00943887047f);
        p = fmaf(p, w, 1.00167406f);
        p = fmaf(p, w, 2.83297682f);
    }
    return 1.41421356f * (p * u);
}

__global__ void noise_kernel() {
    const int total = 2 * TT * BB * SS;
    int i = blockIdx.x * blockDim.x + threadIdx.x;
    if (i >= total) return;
    const uint32_t k0 = 0u, k1 = 42u;
    const uint32_t k2 = k0 ^ k1 ^ 0x1BD11BDAu;
    uint32_t x0 = 0u;
    uint32_t x1 = (uint32_t)i;
    x0 += k0; x1 += k1;
#define RND(r) { x0 += x1; x1 = rotl32(x1, r); x1 ^= x0; }
    RND(13) RND(15) RND(26) RND(6)   x0 += k1; x1 += k2 + 1u;
    RND(17) RND(29) RND(16) RND(24)  x0 += k2; x1 += k0 + 2u;
    RND(13) RND(15) RND(26) RND(6)   x0 += k0; x1 += k1 + 3u;
    RND(17) RND(29) RND(16) RND(24)  x0 += k1; x1 += k2 + 4u;
    RND(13) RND(15) RND(26) RND(6)   x0 += k2; x1 += k0 + 5u;
#undef RND
    g_noise[i] = normal_from_bits(x0 ^ x1);
}

__global__ void init_kernel(const float* __restrict__ prev_state,
                            const float* __restrict__ prev_belief) {
    int i = blockIdx.x * blockDim.x + threadIdx.x;
    if (i == 0) { g_arrive = 0; g_release = 0; g_ticket = 0; }
    if (i < BB * SS) g_state[i] = prev_state[i];
    if (i < BB * HH) g_belief[i] = prev_belief[i];
}

// ------------- GEMM tile (FFMA2, 128x128, 8x8 microtile, dbl-buffered) -----
struct TileOp {
    const float* A0; int lda; int K0;
    int nSum; size_t sumStride;
    const float* Aextra;            // optional extra matrix summand (same lda)
    const float* Acb;               // optional per-k bias on A
    int reluA;
    const float* rowscale;
    const float* A1; int K1;        // optional concat block, row stride K1
    const float* W;                 // [K, N] row-major (pre-offset for K-split)
    const float* bias;              // [N] or null
    float* C; int N;
    int relu;
};

#define ASW 132                     // row stride: float4-aligned (132*4=528=33*16)

__device__ void gemm_tile(const TileOp op, int m0, int n0,
                          float As[2][16][ASW], float Ws[2][16][128]) {
    __syncthreads();                 // smem reuse guard
    const int t = threadIdx.x;
    const int tx = t & 15, ty = t >> 4;
    const int K = op.K0 + op.K1;
    const int nchunks = K >> 4;

    const int am = t >> 1;           // 0..127 (row)
    const int ak = (t & 1) << 3;     // 0 or 8 (k base)
    const int gm = m0 + am;
    const float rs = op.rowscale ? op.rowscale[gm] : 1.0f;
    const int wk0 = t >> 5;
    const int wn0 = (t & 31) << 2;
    const int wk1 = (t + 256) >> 5;

    unsigned long long acc[8][4];
#pragma unroll
    for (int i = 0; i < 8; ++i)
#pragma unroll
        for (int j = 0; j < 4; ++j) acc[i][j] = 0ull;

    float4 aR0, aR1, wReg0, wReg1;

    auto loadA4 = [&](int gk) -> float4 {
        if (gk < op.K0) {
            const float* a = op.A0 + (size_t)gm * op.lda + gk;
            float4 v = *(const float4*)a;
            for (int j = 1; j < op.nSum; ++j) {
                const float4 e = *(const float4*)(a + (size_t)j * op.sumStride);
                v.x += e.x; v.y += e.y; v.z += e.z; v.w += e.w;
            }
            if (op.Aextra) {
                const float4 e = *(const float4*)(op.Aextra + (size_t)gm * op.lda + gk);
                v.x += e.x; v.y += e.y; v.z += e.z; v.w += e.w;
            }
            if (op.Acb) {
                const float4 e = *(const float4*)(op.Acb + gk);
                v.x += e.x; v.y += e.y; v.z += e.z; v.w += e.w;
            }
            if (op.reluA) {
                v.x = fmaxf(v.x, 0.0f); v.y = fmaxf(v.y, 0.0f);
                v.z = fmaxf(v.z, 0.0f); v.w = fmaxf(v.w, 0.0f);
            }
            v.x *= rs; v.y *= rs; v.z *= rs; v.w *= rs;
            return v;
        }
        return *(const float4*)(op.A1 + (size_t)gm * op.K1 + (gk - op.K0));
    };

    auto load_regs = [&](int c) {
        int gk = (c << 4) + ak;
        aR0 = loadA4(gk);
        aR1 = loadA4(gk + 4);
        const float* wbase = op.W + (size_t)(c << 4) * op.N + n0;
        wReg0 = *(const float4*)(wbase + (size_t)wk0 * op.N + wn0);
        wReg1 = *(const float4*)(wbase + (size_t)wk1 * op.N + wn0);
    };
    auto sts = [&](int b) {
        As[b][ak + 0][am] = aR0.x; As[b][ak + 1][am] = aR0.y;
        As[b][ak + 2][am] = aR0.z; As[b][ak + 3][am] = aR0.w;
        As[b][ak + 4][am] = aR1.x; As[b][ak + 5][am] = aR1.y;
        As[b][ak + 6][am] = aR1.z; As[b][ak + 7][am] = aR1.w;
        *(float4*)&Ws[b][wk0][wn0] = wReg0;
        *(float4*)&Ws[b][wk1][wn0] = wReg1;
    };

    load_regs(0);
    sts(0);
    __syncthreads();

    int buf = 0;
    for (int c = 0; c < nchunks; ++c) {
        const bool has_next = (c + 1 < nchunks);
        if (has_next) load_regs(c + 1);
#pragma unroll
        for (int kk = 0; kk < 16; ++kk) {
            float4 a0 = *(const float4*)&As[buf][kk][ty << 3];
            float4 a1 = *(const float4*)&As[buf][kk][(ty << 3) + 4];
            unsigned long long ap0 = pack2(a0.x, a0.x);
            unsigned long long ap1 = pack2(a0.y, a0.y);
            unsigned long long ap2 = pack2(a0.z, a0.z);
            unsigned long long ap3 = pack2(a0.w, a0.w);
            unsigned long long ap4 = pack2(a1.x, a1.x);
            unsigned long long ap5 = pack2(a1.y, a1.y);
            unsigned long long ap6 = pack2(a1.z, a1.z);
            unsigned long long ap7 = pack2(a1.w, a1.w);
            const unsigned long long* wr =
                (const unsigned long long*)(&Ws[buf][kk][tx << 3]);
            unsigned long long w0 = wr[0], w1 = wr[1], w2 = wr[2], w3 = wr[3];
            acc[0][0] = ffma2(ap0, w0, acc[0][0]);
            acc[0][1] = ffma2(ap0, w1, acc[0][1]);
            acc[0][2] = ffma2(ap0, w2, acc[0][2]);
            acc[0][3] = ffma2(ap0, w3, acc[0][3]);
            acc[1][0] = ffma2(ap1, w0, acc[1][0]);
            acc[1][1] = ffma2(ap1, w1, acc[1][1]);
            acc[1][2] = ffma2(ap1, w2, acc[1][2]);
            acc[1][3] = ffma2(ap1, w3, acc[1][3]);
            acc[2][0] = ffma2(ap2, w0, acc[2][0]);
            acc[2][1] = ffma2(ap2, w1, acc[2][1]);
            acc[2][2] = ffma2(ap2, w2, acc[2][2]);
            acc[2][3] = ffma2(ap2, w3, acc[2][3]);
            acc[3][0] = ffma2(ap3, w0, acc[3][0]);
            acc[3][1] = ffma2(ap3, w1, acc[3][1]);
            acc[3][2] = ffma2(ap3, w2, acc[3][2]);
            acc[3][3] = ffma2(ap3, w3, acc[3][3]);
            acc[4][0] = ffma2(ap4, w0, acc[4][0]);
            acc[4][1] = ffma2(ap4, w1, acc[4][1]);
            acc[4][2] = ffma2(ap4, w2, acc[4][2]);
            acc[4][3] = ffma2(ap4, w3, acc[4][3]);
            acc[5][0] = ffma2(ap5, w0, acc[5][0]);
            acc[5][1] = ffma2(ap5, w1, acc[5][1]);
            acc[5][2] = ffma2(ap5, w2, acc[5][2]);
            acc[5][3] = ffma2(ap5, w3, acc[5][3]);
            acc[6][0] = ffma2(ap6, w0, acc[6][0]);
            acc[6][1] = ffma2(ap6, w1, acc[6][1]);
            acc[6][2] = ffma2(ap6, w2, acc[6][2]);
            acc[6][3] = ffma2(ap6, w3, acc[6][3]);
            acc[7][0] = ffma2(ap7, w0, acc[7][0]);
            acc[7][1] = ffma2(ap7, w1, acc[7][1]);
            acc[7][2] = ffma2(ap7, w2, acc[7][2]);
            acc[7][3] = ffma2(ap7, w3, acc[7][3]);
        }
        if (has_next) {
            sts(buf ^ 1);
            __syncthreads();
            buf ^= 1;
        }
    }

    const int nb = n0 + (tx << 3);
    const int mb = m0 + (ty << 3);
    float bs[8];
#pragma unroll
    for (int c = 0; c < 8; ++c) bs[c] = op.bias ? op.bias[nb + c] : 0.0f;
#pragma unroll
    for (int i = 0; i < 8; ++i) {
        float o[8];
#pragma unroll
        for (int j = 0; j < 4; ++j) unpack2(acc[i][j], o[2 * j], o[2 * j + 1]);
#pragma unroll
        for (int c = 0; c < 8; ++c) {
            o[c] += bs[c];
            if (op.relu) o[c] = fmaxf(o[c], 0.0f);
        }
        float4* dst = (float4*)(op.C + (size_t)(mb + i) * op.N + nb);
        dst[0] = make_float4(o[0], o[1], o[2], o[3]);
        dst[1] = make_float4(o[4], o[5], o[6], o[7]);
    }
}

// Static-grid tile launcher (pre/post big GEMMs)
__global__ __launch_bounds__(256, 2) void gemm_big(TileOp op) {
    __shared__ __align__(16) float As[2][16][ASW];
    __shared__ __align__(16) float Ws[2][16][128];
    gemm_tile(op, blockIdx.y * 128, blockIdx.x * 128, As, Ws);
}

// ---------------- persistent scan kernel (posterior critical path) ---------
__global__ __launch_bounds__(256, 2) void rssm_kernel(
    const float* __restrict__ actions,
    const float* __restrict__ nonterminals,
    const float* __restrict__ W_sa, const float* __restrict__ b_sa,
    const float* __restrict__ W_x,  const float* __restrict__ W_h,
    const float* __restrict__ b_x,  const float* __restrict__ b_h,
    const float* __restrict__ W_bq, const float* __restrict__ b_bq,
    const float* __restrict__ W_sq, const float* __restrict__ b_sq,
    float* __restrict__ out, int full)
{
    __shared__ __align__(16) float As[2][16][ASW];
    __shared__ __align__(16) float Ws[2][16][128];
    __shared__ unsigned sPiece;
    const int bid = blockIdx.x;
    const int stride = gridDim.x;
    const int tid = threadIdx.x;
    unsigned gen = 0;

    const size_t O_BEL  = 0;
    const size_t O_POST = (size_t)TT * BB * HH + 3 * (size_t)TT * BB * SS;
    const size_t O_QM   = O_POST + (size_t)TT * BB * SS;
    const size_t O_QS   = O_QM   + (size_t)TT * BB * SS;

    auto grab = [&]() -> unsigned {
        __syncthreads();
        if (tid == 0) sPiece = atomicAdd(&g_ticket, 1);
        __syncthreads();
        return sPiece;
    };

    for (int t = 0; t < TT; ++t) {
        const float* a_t  = actions + (size_t)t * BB * AA;
        const float* nt_t = nonterminals + (size_t)t * BB;
        const float* qo_t = g_qobs + (size_t)t * BB * HH;

        // Phase A: h1 (16 pieces, 128-tiles) + hg K-split4 (192 pieces)
        for (unsigned p = grab(); p < 208; p = grab()) {
            if (p < 16) {
                TileOp op{g_state, SS, SS, 1, 0, nullptr, nullptr, 0, nt_t,
                          a_t, AA, W_sa, b_sa, g_h1, HH, 1};
                gemm_tile(op, (int)(p & 1) * 128, (int)(p >> 1) * 128, As, Ws);
            } else {
                unsigned q = p - 16;
                int ks = q & 3, tile = q >> 2;      // tile 0..47
                TileOp op{g_belief + ks * 256, HH, 256, 1, 0, nullptr, nullptr, 0,
                          nullptr, nullptr, 0, W_h + (size_t)ks * 256 * 3 * HH,
                          nullptr, g_hg4 + (size_t)ks * B3H, 3 * HH, 0};
                gemm_tile(op, (tile & 1) * 128, (tile >> 1) * 128, As, Ws);
            }
        }
        grid_bar(++gen);

        // Phase B: xg K-split4 (192 pieces)
        for (unsigned p = grab(); p < 192; p = grab()) {
            int ks = p & 3, tile = p >> 2;
            TileOp op{g_h1 + ks * 256, HH, 256, 1, 0, nullptr, nullptr, 0,
                      nullptr, nullptr, 0, W_x + (size_t)ks * 256 * 3 * HH,
                      nullptr, g_xg4 + (size_t)ks * B3H, 3 * HH, 0};
            gemm_tile(op, (tile & 1) * 128, (tile >> 1) * 128, As, Ws);
        }
        grid_bar(++gen);

        // Phase C: GRU elementwise (sums partials) -> belief (+ output)
        {
            float* ob = out + O_BEL + (size_t)t * BB * HH;
            for (int idx = bid * 256 + tid; idx < BB * HH; idx += stride * 256) {
                int b = idx >> 10, j = idx & 1023;
                size_t base = (size_t)b * 3072 + j;
                float xz = b_x[j], xr = b_x[1024 + j], xh = b_x[2048 + j];
                float hz = b_h[j], hr = b_h[1024 + j], hh = b_h[2048 + j];
#pragma unroll
                for (int jp = 0; jp < 4; ++jp) {
                    const float* xp = g_xg4 + (size_t)jp * B3H + base;
                    const float* hp = g_hg4 + (size_t)jp * B3H + base;
                    xz += xp[0]; xr += xp[1024]; xh += xp[2048];
                    hz += hp[0]; hr += hp[1024]; hh += hp[2048];
                }
                float z = sigmoidf_(xz + hz);
                float r = sigmoidf_(xr + hr);
                float cand = tanhf(xh + r * hh);
                float bo = g_belief[idx];
                float bn = z * bo + (1.0f - z) * cand;
                g_belief[idx] = bn;
                ob[idx] = bn;
            }
        }
        grid_bar(++gen);

        // Phase D: q1 = bel @ W_bq[:H]  K-split8 (128 pieces, partials)
        for (unsigned p = grab(); p < 128; p = grab()) {
            int ks = p & 7, tile = p >> 3;          // tile 0..15
            TileOp op{g_belief + ks * 128, HH, 128, 1, 0, nullptr, nullptr, 0,
                      nullptr, nullptr, 0, W_bq + (size_t)ks * 128 * HH,
                      nullptr, g_q18 + (size_t)ks * BH, HH, 0};
            gemm_tile(op, (tile & 1) * 128, (tile >> 1) * 128, As, Ws);
        }
        grid_bar(++gen);

        // Phase E: qh = relu(sum q1 + qobs + b_bq) @ W_sq  K-split8 (64 pieces)
        for (unsigned p = grab(); p < 64; p = grab()) {
            int ks = p & 7, tile = p >> 3;          // tile 0..7
            TileOp op{g_q18 + ks * 128, HH, 128, 8, (size_t)BH, qo_t + ks * 128,
                      b_bq + ks * 128, 1, nullptr, nullptr, 0,
                      W_sq + (size_t)ks * 128 * 2 * SS,
                      nullptr, g_qh8 + (size_t)ks * B2S, 2 * SS, 0};
            gemm_tile(op, (tile & 1) * 128, (tile >> 1) * 128, As, Ws);
        }
        grid_bar(++gen);

        // Phase F: posterior heads (sums qh partials) -> outputs + next state
        {
            const float* nQ = g_noise + (size_t)(TT + t) * BB * SS;
            for (int idx = bid * 256 + tid; idx < BB * SS; idx += stride * 256) {
                int b = idx >> 8, s = idx & 255;
                float qm = b_sq[s], qsr = b_sq[256 + s];
#pragma unroll
                for (int jp = 0; jp < 8; ++jp) {
                    const float* qp = g_qh8 + (size_t)jp * B2S + b * 512 + s;
                    qm += qp[0]; qsr += qp[256];
                }
                float qs = softplusf_(qsr) + 0.1f;
                float po = qm + qs * nQ[idx];
                if (full) {
                    size_t o = (size_t)t * BB * SS + idx;
                    out[O_QM + o] = qm; out[O_QS + o] = qs; out[O_POST + o] = po;
                }
                g_state[idx] = po;
            }
        }
        grid_bar(++gen);
    }
}

// ---------------- prior heads elementwise (post-pass) ----------------
__global__ void prior_heads_kernel(float* __restrict__ out, int full) {
    const size_t O_PRI = (size_t)TT * BB * HH;
    const size_t O_PM  = O_PRI + (size_t)TT * BB * SS;
    const size_t O_PS  = O_PM  + (size_t)TT * BB * SS;
    int idx = blockIdx.x * blockDim.x + threadIdx.x;   // over T*B*S
    if (idx >= TT * BB * SS) return;
    int r = idx >> 8, s = idx & 255;
    float pm = g_phall[(size_t)r * 512 + s];
    float ps = softplusf_(g_phall[(size_t)r * 512 + 256 + s]) + 0.1f;
    float pr = pm + ps * g_noise[idx];
    if (full) { out[O_PM + idx] = pm; out[O_PS + idx] = ps; out[O_PRI + idx] = pr; }
}

// ---------------- launch ----------------
extern "C" void kernel_launch(void* const* d_in, const int* in_sizes, int n_in,
                              void* d_out, int out_size) {
    const float* actions      = (const float*)d_in[0];
    const float* prev_state   = (const float*)d_in[1];
    const float* prev_belief  = (const float*)d_in[2];
    const float* observations = (const float*)d_in[3];
    const float* nonterminals = (const float*)d_in[4];
    const float* W_sa = (const float*)d_in[5];
    const float* b_sa = (const float*)d_in[6];
    const float* W_x  = (const float*)d_in[7];
    const float* W_h  = (const float*)d_in[8];
    const float* b_x  = (const float*)d_in[9];
    const float* b_h  = (const float*)d_in[10];
    const float* W_bp = (const float*)d_in[11];
    const float* b_bp = (const float*)d_in[12];
    const float* W_sp = (const float*)d_in[13];
    const float* b_sp = (const float*)d_in[14];
    const float* W_bq = (const float*)d_in[15];
    const float* b_bq = (const float*)d_in[16];
    const float* W_sq = (const float*)d_in[17];
    const float* b_sq = (const float*)d_in[18];
    float* out = (float*)d_out;

    const size_t FULL = (size_t)TT * BB * (HH + 6 * SS);
    const int full = (size_t)out_size >= FULL;

    float *qobs, *phall;
    cudaGetSymbolAddress((void**)&qobs, g_qobs);
    cudaGetSymbolAddress((void**)&phall, g_phall);

    noise_kernel<<<(2 * TT * BB * SS + 255) / 256, 256>>>();
    init_kernel<<<(BB * HH + 255) / 256, 256>>>(prev_state, prev_belief);

    // Pre: qobs[t] = obs[t] @ W_bq[H:, :]   ([12800,1024] x [1024,1024])
    {
        TileOp op{observations, OO, OO, 1, 0, nullptr, nullptr, 0, nullptr,
                  nullptr, 0, W_bq + (size_t)HH * HH, nullptr, qobs, HH, 0};
        gemm_big<<<dim3(HH / 128, (TT * BB) / 128), 256>>>(op);
    }

    // Scan (posterior critical path only)
    rssm_kernel<<<NCTA, 256>>>(actions, nonterminals,
                               W_sa, b_sa, W_x, W_h, b_x, b_h,
                               W_bq, b_bq, W_sq, b_sq, out, full);

    // Post: prior branch batched over all T
    // p1_all = relu(belief_all @ W_bp + b_bp)   (reuses g_qobs as scratch)
    {
        TileOp op{out /*O_BEL*/, HH, HH, 1, 0, nullptr, nullptr, 0, nullptr,
                  nullptr, 0, W_bp, b_bp, qobs, HH, 1};
        gemm_big<<<dim3(HH / 128, (TT * BB) / 128), 256>>>(op);
    }
    // ph_all = p1_all @ W_sp + b_sp
    {
        TileOp op{qobs, HH, HH, 1, 0, nullptr, nullptr, 0, nullptr,
                  nullptr, 0, W_sp, b_sp, phall, 2 * SS, 0};
        gemm_big<<<dim3(2 * SS / 128, (TT * BB) / 128), 256>>>(op);
    }
    prior_heads_kernel<<<(TT * BB * SS + 255) / 256, 256>>>(out, full);
}

// round 15
// speedup vs baseline: 1.4689x; 1.3587x over previous
#include <cuda_runtime.h>
#include <cuda_bf16.h>
#include <cstdint>
#include <math.h>

// Problem dims (fixed by setup_inputs)
#define TT 50
#define BB 256
#define AA 64
#define SS 256
#define HH 1024
#define OO 1024
#define NCTA 148
#define BH  (BB * HH)
#define B3H (BB * 3 * HH)
#define B2S (BB * 2 * SS)
#define TBH (TT * BB * HH)

typedef unsigned short u16;
typedef uint32_t u32;

// ---------------- device scratch (static allocation only) ----------------
__device__ float g_noise[2 * TT * BB * SS];
__device__ float g_qobs[TBH];                       // obs @ W_bq[H:]
__device__ float g_phall[TT * BB * 2 * SS];
__device__ float g_belief[BH];
__device__ float g_hg[B3H];
__device__ float g_xg[B3H];
__device__ float g_qh[B2S];
// bf16 hi/lo activation splits
__device__ __align__(128) u16 g_bel_h[BH],  g_bel_l[BH];
__device__ __align__(128) u16 g_st_h[BB*SS], g_st_l[BB*SS];
__device__ __align__(128) u16 g_h1h[BH],  g_h1l[BH];
__device__ __align__(128) u16 g_q1h[BH],  g_q1l[BH];
__device__ __align__(128) u16 g_acth[TT*BB*AA], g_actl[TT*BB*AA];
__device__ __align__(128) u16 g_obsh[TT*BB*OO], g_obsl[TT*BB*OO];
__device__ __align__(128) u16 g_bah[TBH], g_bal[TBH];      // belief_all splits
__device__ __align__(128) u16 g_p1h[TBH], g_p1l[TBH];      // p1_all splits
// transposed bf16 weights [N, K]
__device__ __align__(128) u16 g_wsa_h[HH*320],   g_wsa_l[HH*320];
__device__ __align__(128) u16 g_wx_h[3*HH*HH],   g_wx_l[3*HH*HH];
__device__ __align__(128) u16 g_wh_h[3*HH*HH],   g_wh_l[3*HH*HH];
__device__ __align__(128) u16 g_wbq_h[HH*HH],    g_wbq_l[HH*HH];     // top half
__device__ __align__(128) u16 g_wbqo_h[HH*HH],   g_wbqo_l[HH*HH];    // bottom half
__device__ __align__(128) u16 g_wsq_h[2*SS*HH],  g_wsq_l[2*SS*HH];
__device__ __align__(128) u16 g_wbp_h[HH*HH],    g_wbp_l[HH*HH];
__device__ __align__(128) u16 g_wsp_h[2*SS*HH],  g_wsp_l[2*SS*HH];
__device__ unsigned g_arrive;
__device__ unsigned g_release;
__device__ unsigned g_ticket;

// ---------------- helpers ----------------
__device__ __forceinline__ float sigmoidf_(float x) { return 1.0f / (1.0f + expf(-x)); }
__device__ __forceinline__ float softplusf_(float x) {
    return fmaxf(x, 0.0f) + log1pf(expf(-fabsf(x)));
}
__device__ __forceinline__ unsigned ld_acquire(unsigned* p) {
    unsigned v;
    asm volatile("ld.acquire.gpu.u32 %0, [%1];" : "=r"(v) : "l"(p));
    return v;
}
__device__ __forceinline__ u16 f2bf(float x) {
    __nv_bfloat16 b = __float2bfloat16(x);
    return *reinterpret_cast<u16*>(&b);
}
__device__ __forceinline__ float bf2f(u16 u) {
    __nv_bfloat16 b = *reinterpret_cast<__nv_bfloat16*>(&u);
    return __bfloat162float(b);
}
__device__ __forceinline__ u32 smem_u32(const void* p) {
    u32 a;
    asm("{ .reg .u64 t; cvta.to.shared.u64 t, %1; cvt.u32.u64 %0, t; }"
        : "=r"(a) : "l"(p));
    return a;
}

// ---------------- MMA primitives (baseline PTX, legal at compute_103) ------
__device__ __forceinline__ void ldsm4(u32* r, u32 addr) {
    asm volatile("ldmatrix.sync.aligned.m8n8.x4.shared.b16 {%0,%1,%2,%3}, [%4];"
                 : "=r"(r[0]), "=r"(r[1]), "=r"(r[2]), "=r"(r[3]) : "r"(addr));
}
__device__ __forceinline__ void mma16816(float* c, const u32* a, const u32* b) {
    asm volatile(
        "mma.sync.aligned.m16n8k16.row.col.f32.bf16.bf16.f32 "
        "{%0,%1,%2,%3}, {%4,%5,%6,%7}, {%8,%9}, {%0,%1,%2,%3};"
        : "+f"(c[0]), "+f"(c[1]), "+f"(c[2]), "+f"(c[3])
        : "r"(a[0]), "r"(a[1]), "r"(a[2]), "r"(a[3]), "r"(b[0]), "r"(b[1]));
}

// ---------------- grid-wide barrier + ticket reset ----------------
__device__ __forceinline__ void grid_bar(unsigned gen) {
    __syncthreads();
    if (threadIdx.x == 0) {
        __threadfence();
        if (atomicAdd(&g_arrive, 1) == gridDim.x - 1) {
            g_arrive = 0;
            g_ticket = 0;
            __threadfence();
            atomicExch(&g_release, gen);
        } else {
            while (ld_acquire(&g_release) < gen) __nanosleep(32);
        }
    }
    __syncthreads();
}

// ---------------- JAX threefry2x32 noise (key = (0,42)) ----------------
__device__ __forceinline__ u32 rotl32(u32 x, int r) { return (x << r) | (x >> (32 - r)); }
__device__ __forceinline__ float normal_from_bits(u32 bits) {
    u32 fb = (bits >> 9) | 0x3f800000u;
    float f = __uint_as_float(fb) - 1.0f;
    const float lo = -0.99999994f;
    float u = f * 2.0f + lo;
    u = fmaxf(lo, u);
    float w = -log1pf(-u * u);
    float p;
    if (w < 5.0f) {
        w -= 2.5f;
        p = 2.81022636e-08f;
        p = fmaf(p, w, 3.43273939e-07f);
        p = fmaf(p, w, -3.5233877e-06f);
        p = fmaf(p, w, -4.39150654e-06f);
        p = fmaf(p, w, 0.00021858087f);
        p = fmaf(p, w, -0.00125372503f);
        p = fmaf(p, w, -0.00417768164f);
        p = fmaf(p, w, 0.246640727f);
        p = fmaf(p, w, 1.50140941f);
    } else {
        w = sqrtf(w) - 3.0f;
        p = -0.000200214257f;
        p = fmaf(p, w, 0.000100950558f);
        p = fmaf(p, w, 0.00134934322f);
        p = fmaf(p, w, -0.00367342844f);
        p = fmaf(p, w, 0.00573950773f);
        p = fmaf(p, w, -0.0076224613f);
        p = fmaf(p, w, 0.00943887047f);
        p = fmaf(p, w, 1.00167406f);
        p = fmaf(p, w, 2.83297682f);
    }
    return 1.41421356f * (p * u);
}

__global__ void noise_kernel() {
    const int total = 2 * TT * BB * SS;
    int i = blockIdx.x * blockDim.x + threadIdx.x;
    if (i >= total) return;
    const u32 k0 = 0u, k1 = 42u;
    const u32 k2 = k0 ^ k1 ^ 0x1BD11BDAu;
    u32 x0 = 0u, x1 = (u32)i;
    x0 += k0; x1 += k1;
#define RND(r) { x0 += x1; x1 = rotl32(x1, r); x1 ^= x0; }
    RND(13) RND(15) RND(26) RND(6)   x0 += k1; x1 += k2 + 1u;
    RND(17) RND(29) RND(16) RND(24)  x0 += k2; x1 += k0 + 2u;
    RND(13) RND(15) RND(26) RND(6)   x0 += k0; x1 += k1 + 3u;
    RND(17) RND(29) RND(16) RND(24)  x0 += k1; x1 += k2 + 4u;
    RND(13) RND(15) RND(26) RND(6)   x0 += k2; x1 += k0 + 5u;
#undef RND
    g_noise[i] = normal_from_bits(x0 ^ x1);
}

__global__ void init_kernel(const float* __restrict__ prev_state,
                            const float* __restrict__ prev_belief,
                            const float* __restrict__ nonterminals) {
    int i = blockIdx.x * blockDim.x + threadIdx.x;
    if (i == 0) { g_arrive = 0; g_release = 0; g_ticket = 0; }
    if (i < BB * SS) {
        float sm = prev_state[i] * nonterminals[i >> 8];
        u16 h = f2bf(sm);
        g_st_h[i] = h; g_st_l[i] = f2bf(sm - bf2f(h));
    }
    if (i < BB * HH) {
        float v = prev_belief[i];
        g_belief[i] = v;
        u16 h = f2bf(v);
        g_bel_h[i] = h; g_bel_l[i] = f2bf(v - bf2f(h));
    }
}

// split+transpose: W[K,N] -> Wt_hi/lo[N,K]
__global__ void wsplit_kernel(const float* __restrict__ W, int K, int N,
                              u16* __restrict__ th, u16* __restrict__ tl) {
    long long i = (long long)blockIdx.x * 256 + threadIdx.x;
    if (i >= (long long)K * N) return;
    int n = (int)(i / K), k = (int)(i % K);
    float v = W[(size_t)k * N + n];
    u16 h = f2bf(v);
    th[i] = h; tl[i] = f2bf(v - bf2f(h));
}

__global__ void split_kernel(const float* __restrict__ a, long long n,
                             u16* __restrict__ oh, u16* __restrict__ ol) {
    long long i = (long long)blockIdx.x * 256 + threadIdx.x;
    if (i >= n) return;
    float v = a[i];
    u16 h = f2bf(v);
    oh[i] = h; ol[i] = f2bf(v - bf2f(h));
}

// ---------------- HMMA tile engine ----------------
// smem: 2 buffers x (Ah, Al, Bh, Bl), each 128 rows x 32 bf16 padded to 80B/row.
#define ROWB 80
#define MATB (128 * ROWB)            // 10240
#define BUFB (4 * MATB)              // 40960
#define ENG_SMEM (2 * BUFB)          // 81920
#define OF_AH 0
#define OF_AL MATB
#define OF_BH (2 * MATB)
#define OF_BL (3 * MATB)

struct MOp {
    const u16 *ah, *al; int lda; int k0;    // A block0 (pre-offset to tile m0)
    const u16 *a1h, *a1l; int lda1;         // concat block (k >= k0)
    const u16 *bh, *bl; int ldb;            // B = Wt rows (pre-offset n0)
    int K;                                  // multiple of 32
    int mrows;                              // 128 or 64
    const float* bias;                      // pre-offset n0 (or null)
    const float* add; int ldadd;            // pre-offset (or null)
    float* outf; int ldout;                 // pre-offset (or null)
    u16 *oh, *ol; int ldoh;                 // pre-offset (or null)
    int relu;
};

__device__ void mma_tile(const MOp op, char* sm, u32 su) {
    const int tid = threadIdx.x;
    const int lane = tid & 31;
    const int wid = tid >> 5;
    const int nch = op.K >> 5;

    const bool m128 = (op.mrows == 128);
    const int wm = m128 ? (wid & 1) * 64 : 0;
    const int wnb = m128 ? (wid >> 1) * 32 : wid * 16;
    const int na = m128 ? 4 : 2;

    // staging ids
    const int arow = tid >> 1;
    const int half = tid & 1;
    const bool doA = arow < op.mrows;

    float acc[4][4][4];
#pragma unroll
    for (int i = 0; i < 4; ++i)
#pragma unroll
        for (int j = 0; j < 4; ++j)
#pragma unroll
            for (int k = 0; k < 4; ++k) acc[i][j][k] = 0.0f;

    uint4 pah[2], pal[2], pbh[2], pbl[2];
    auto load_regs = [&](int c) {
        int kc = c << 5;
        if (doA) {
            const u16 *sh, *sl; int ld;
            if (kc < op.k0) { sh = op.ah + kc; sl = op.al + kc; ld = op.lda; }
            else { sh = op.a1h + (kc - op.k0); sl = op.a1l + (kc - op.k0); ld = op.lda1; }
            const uint4* ph = (const uint4*)(sh + (size_t)arow * ld + half * 16);
            const uint4* pl = (const uint4*)(sl + (size_t)arow * ld + half * 16);
            pah[0] = ph[0]; pah[1] = ph[1];
            pal[0] = pl[0]; pal[1] = pl[1];
        }
        const uint4* qh = (const uint4*)(op.bh + (size_t)arow * op.ldb + kc + half * 16);
        const uint4* ql = (const uint4*)(op.bl + (size_t)arow * op.ldb + kc + half * 16);
        pbh[0] = qh[0]; pbh[1] = qh[1];
        pbl[0] = ql[0]; pbl[1] = ql[1];
    };
    auto sts = [&](int b) {
        char* base = sm + b * BUFB;
        int off = arow * ROWB + half * 32;
        if (doA) {
            *(uint4*)(base + OF_AH + off) = pah[0];
            *(uint4*)(base + OF_AH + off + 16) = pah[1];
            *(uint4*)(base + OF_AL + off) = pal[0];
            *(uint4*)(base + OF_AL + off + 16) = pal[1];
        }
        *(uint4*)(base + OF_BH + off) = pbh[0];
        *(uint4*)(base + OF_BH + off + 16) = pbh[1];
        *(uint4*)(base + OF_BL + off) = pbl[0];
        *(uint4*)(base + OF_BL + off + 16) = pbl[1];
    };

    // fragment address components
    const int a_row0 = wm + (lane & 7) + ((lane >> 3) & 1) * 8;
    const int a_kb0  = ((lane >> 4) & 1) * 16;
    const int b_row0 = wnb + (lane & 7) + ((lane >> 4) & 1) * 8;
    const int b_kb0  = ((lane >> 3) & 1) * 16;

    __syncthreads();
    load_regs(0);
    sts(0);
    __syncthreads();

    int buf = 0;
    for (int c = 0; c < nch; ++c) {
        const bool hn = (c + 1 < nch);
        if (hn) load_regs(c + 1);
        u32 bb = su + buf * BUFB;
#pragma unroll
        for (int ks = 0; ks < 2; ++ks) {
            u32 ah[4][4], al[4][4], bh[4][2], bl[4][2];
#pragma unroll
            for (int am = 0; am < 4; ++am) {
                u32 ra = bb + OF_AH + (u32)(a_row0 + am * 16) * ROWB + ks * 32 + a_kb0;
                ldsm4(ah[am], ra);
                ldsm4(al[am], ra + (OF_AL - OF_AH));
            }
#pragma unroll
            for (int p = 0; p < 2; ++p) {
                if (p * 2 >= na) break;
                u32 rb = bb + OF_BH + (u32)(b_row0 + p * 16) * ROWB + ks * 32 + b_kb0;
                u32 t[4];
                ldsm4(t, rb);
                bh[2 * p][0] = t[0]; bh[2 * p][1] = t[1];
                bh[2 * p + 1][0] = t[2]; bh[2 * p + 1][1] = t[3];
                ldsm4(t, rb + (OF_BL - OF_BH));
                bl[2 * p][0] = t[0]; bl[2 * p][1] = t[1];
                bl[2 * p + 1][0] = t[2]; bl[2 * p + 1][1] = t[3];
            }
#pragma unroll
            for (int am = 0; am < 4; ++am)
#pragma unroll
                for (int an = 0; an < 4; ++an) {
                    if (an >= na) break;
                    mma16816(acc[am][an], ah[am], bh[an]);
                    mma16816(acc[am][an], ah[am], bl[an]);
                    mma16816(acc[am][an], al[am], bh[an]);
                }
        }
        if (hn) {
            sts(buf ^ 1);
            __syncthreads();
            buf ^= 1;
        }
    }

    // epilogue
    auto emit = [&](int row, int col, float v0, float v1) {
        if (op.bias) { v0 += op.bias[col]; v1 += op.bias[col + 1]; }
        if (op.add) {
            const float* ar = op.add + (size_t)row * op.ldadd + col;
            v0 += ar[0]; v1 += ar[1];
        }
        if (op.relu) { v0 = fmaxf(v0, 0.0f); v1 = fmaxf(v1, 0.0f); }
        if (op.outf) {
            *(float2*)(op.outf + (size_t)row * op.ldout + col) = make_float2(v0, v1);
        }
        if (op.oh) {
            u16 h0 = f2bf(v0), h1 = f2bf(v1);
            ushort2 hh = make_ushort2(h0, h1);
            ushort2 ll = make_ushort2(f2bf(v0 - bf2f(h0)), f2bf(v1 - bf2f(h1)));
            *(ushort2*)(op.oh + (size_t)row * op.ldoh + col) = hh;
            *(ushort2*)(op.ol + (size_t)row * op.ldoh + col) = ll;
        }
    };
#pragma unroll
    for (int am = 0; am < 4; ++am)
#pragma unroll
        for (int an = 0; an < 4; ++an) {
            if (an >= na) break;
            int col = wnb + an * 8 + ((lane & 3) << 1);
            int row = wm + am * 16 + (lane >> 2);
            emit(row, col, acc[am][an][0], acc[am][an][1]);
            emit(row + 8, col, acc[am][an][2], acc[am][an][3]);
        }
    __syncthreads();
}

// ---------------- static-grid big GEMM ----------------
struct BigOp {
    const u16 *ah, *al; int lda;
    const u16 *bh, *bl; int ldb;
    int K;
    const float* bias;
    float* outf; int ldout;
    u16 *oh, *ol; int ldoh;
    int relu;
};

__global__ __launch_bounds__(256, 1) void gemm_big(BigOp b) {
    extern __shared__ __align__(128) char smem[];
    int m0 = blockIdx.y * 128, n0 = blockIdx.x * 128;
    MOp op{};
    op.ah = b.ah + (size_t)m0 * b.lda; op.al = b.al + (size_t)m0 * b.lda;
    op.lda = b.lda; op.k0 = b.K;
    op.bh = b.bh + (size_t)n0 * b.ldb; op.bl = b.bl + (size_t)n0 * b.ldb;
    op.ldb = b.ldb; op.K = b.K; op.mrows = 128;
    op.bias = b.bias ? b.bias + n0 : nullptr;
    if (b.outf) { op.outf = b.outf + (size_t)m0 * b.ldout + n0; op.ldout = b.ldout; }
    if (b.oh) {
        op.oh = b.oh + (size_t)m0 * b.ldoh + n0;
        op.ol = b.ol + (size_t)m0 * b.ldoh + n0; op.ldoh = b.ldoh;
    }
    op.relu = b.relu;
    mma_tile(op, smem, smem_u32(smem));
}

// ---------------- persistent scan kernel ----------------
__global__ __launch_bounds__(256, 1) void rssm_kernel(
    const float* __restrict__ nonterminals,
    const float* __restrict__ b_sa,
    const float* __restrict__ b_x,  const float* __restrict__ b_h,
    const float* __restrict__ b_bq, const float* __restrict__ b_sq,
    float* __restrict__ out, int full)
{
    extern __shared__ __align__(128) char smem[];
    __shared__ unsigned sPiece;
    const int bid = blockIdx.x;
    const int stride = gridDim.x;
    const int tid = threadIdx.x;
    unsigned gen = 0;
    u32 su = smem_u32(smem);

    const size_t O_BEL  = 0;
    const size_t O_POST = (size_t)TT * BB * HH + 3 * (size_t)TT * BB * SS;
    const size_t O_QM   = O_POST + (size_t)TT * BB * SS;
    const size_t O_QS   = O_QM   + (size_t)TT * BB * SS;

    auto grab = [&]() -> unsigned {
        __syncthreads();
        if (tid == 0) sPiece = atomicAdd(&g_ticket, 1);
        __syncthreads();
        return sPiece;
    };

    for (int t = 0; t < TT; ++t) {
        // Phase A: h1 (16 tiles 128x128) + hg (48 tiles)
        for (unsigned p = grab(); p < 64; p = grab()) {
            MOp op{};
            if (p < 16) {
                int m0 = (p & 1) * 128, n0 = (int)(p >> 1) * 128;
                op.ah = g_st_h + (size_t)m0 * SS; op.al = g_st_l + (size_t)m0 * SS;
                op.lda = SS; op.k0 = 256;
                op.a1h = g_acth + (size_t)t * BB * AA + (size_t)m0 * AA;
                op.a1l = g_actl + (size_t)t * BB * AA + (size_t)m0 * AA;
                op.lda1 = AA;
                op.bh = g_wsa_h + (size_t)n0 * 320; op.bl = g_wsa_l + (size_t)n0 * 320;
                op.ldb = 320; op.K = 320; op.mrows = 128;
                op.bias = b_sa + n0; op.relu = 1;
                op.oh = g_h1h + (size_t)m0 * HH + n0;
                op.ol = g_h1l + (size_t)m0 * HH + n0; op.ldoh = HH;
            } else {
                unsigned q = p - 16;
                int m0 = (q & 1) * 128, n0 = (int)(q >> 1) * 128;
                op.ah = g_bel_h + (size_t)m0 * HH; op.al = g_bel_l + (size_t)m0 * HH;
                op.lda = HH; op.k0 = HH; op.K = HH; op.mrows = 128;
                op.bh = g_wh_h + (size_t)n0 * HH; op.bl = g_wh_l + (size_t)n0 * HH;
                op.ldb = HH;
                op.outf = g_hg + (size_t)m0 * 3 * HH + n0; op.ldout = 3 * HH;
            }
            mma_tile(op, smem, su);
        }
        grid_bar(++gen);

        // Phase B: xg (48 tiles)
        for (unsigned p = grab(); p < 48; p = grab()) {
            int m0 = (p & 1) * 128, n0 = (int)(p >> 1) * 128;
            MOp op{};
            op.ah = g_h1h + (size_t)m0 * HH; op.al = g_h1l + (size_t)m0 * HH;
            op.lda = HH; op.k0 = HH; op.K = HH; op.mrows = 128;
            op.bh = g_wx_h + (size_t)n0 * HH; op.bl = g_wx_l + (size_t)n0 * HH;
            op.ldb = HH;
            op.outf = g_xg + (size_t)m0 * 3 * HH + n0; op.ldout = 3 * HH;
            mma_tile(op, smem, su);
        }
        grid_bar(++gen);

        // Phase C: GRU elementwise -> belief (+ output + hi/lo + belief_all split)
        {
            float* ob = out + O_BEL + (size_t)t * BB * HH;
            u16* bah = g_bah + (size_t)t * BH;
            u16* bal = g_bal + (size_t)t * BH;
            for (int idx = bid * 256 + tid; idx < BB * HH; idx += stride * 256) {
                int b = idx >> 10, j = idx & 1023;
                size_t base = (size_t)b * 3072 + j;
                float xz = g_xg[base] + b_x[j];
                float xr = g_xg[base + 1024] + b_x[1024 + j];
                float xh = g_xg[base + 2048] + b_x[2048 + j];
                float hz = g_hg[base] + b_h[j];
                float hr = g_hg[base + 1024] + b_h[1024 + j];
                float hh = g_hg[base + 2048] + b_h[2048 + j];
                float z = sigmoidf_(xz + hz);
                float r = sigmoidf_(xr + hr);
                float cand = tanhf(xh + r * hh);
                float bo = g_belief[idx];
                float bn = z * bo + (1.0f - z) * cand;
                g_belief[idx] = bn;
                ob[idx] = bn;
                u16 h = f2bf(bn);
                u16 l = f2bf(bn - bf2f(h));
                g_bel_h[idx] = h; g_bel_l[idx] = l;
                bah[idx] = h; bal[idx] = l;
            }
        }
        grid_bar(++gen);

        // Phase D: q1 = relu(bel @ W_bq_top + qobs + b_bq) (32 tiles 64x128)
        for (unsigned p = grab(); p < 32; p = grab()) {
            int m0 = (int)(p & 3) * 64, n0 = (int)(p >> 2) * 128;
            MOp op{};
            op.ah = g_bel_h + (size_t)m0 * HH; op.al = g_bel_l + (size_t)m0 * HH;
            op.lda = HH; op.k0 = HH; op.K = HH; op.mrows = 64;
            op.bh = g_wbq_h + (size_t)n0 * HH; op.bl = g_wbq_l + (size_t)n0 * HH;
            op.ldb = HH;
            op.bias = b_bq + n0;
            op.add = g_qobs + (size_t)t * BH + (size_t)m0 * HH + n0; op.ldadd = HH;
            op.relu = 1;
            op.oh = g_q1h + (size_t)m0 * HH + n0;
            op.ol = g_q1l + (size_t)m0 * HH + n0; op.ldoh = HH;
            mma_tile(op, smem, su);
        }
        grid_bar(++gen);

        // Phase E: qh = q1 @ W_sq (16 tiles 64x128)
        for (unsigned p = grab(); p < 16; p = grab()) {
            int m0 = (int)(p & 3) * 64, n0 = (int)(p >> 2) * 128;
            MOp op{};
            op.ah = g_q1h + (size_t)m0 * HH; op.al = g_q1l + (size_t)m0 * HH;
            op.lda = HH; op.k0 = HH; op.K = HH; op.mrows = 64;
            op.bh = g_wsq_h + (size_t)n0 * HH; op.bl = g_wsq_l + (size_t)n0 * HH;
            op.ldb = HH;
            op.outf = g_qh + (size_t)m0 * 2 * SS + n0; op.ldout = 2 * SS;
            mma_tile(op, smem, su);
        }
        grid_bar(++gen);

        // Phase F: posterior heads -> outputs + next state
        {
            const float* nQ = g_noise + (size_t)(TT + t) * BB * SS;
            for (int idx = bid * 256 + tid; idx < BB * SS; idx += stride * 256) {
                int b = idx >> 8, s = idx & 255;
                float qm = g_qh[b * 512 + s] + b_sq[s];
                float qs = softplusf_(g_qh[b * 512 + 256 + s] + b_sq[256 + s]) + 0.1f;
                float po = qm + qs * nQ[idx];
                if (full) {
                    size_t o = (size_t)t * BB * SS + idx;
                    out[O_QM + o] = qm; out[O_QS + o] = qs; out[O_POST + o] = po;
                }
                if (t + 1 < TT) {
                    float sm = po * nonterminals[(size_t)(t + 1) * BB + b];
                    u16 h = f2bf(sm);
                    g_st_h[idx] = h; g_st_l[idx] = f2bf(sm - bf2f(h));
                }
            }
        }
        grid_bar(++gen);
    }
}

// ---------------- prior heads elementwise (post-pass) ----------------
__global__ void prior_heads_kernel(float* __restrict__ out, int full) {
    const size_t O_PRI = (size_t)TT * BB * HH;
    const size_t O_PM  = O_PRI + (size_t)TT * BB * SS;
    const size_t O_PS  = O_PM  + (size_t)TT * BB * SS;
    int idx = blockIdx.x * blockDim.x + threadIdx.x;
    if (idx >= TT * BB * SS) return;
    int r = idx >> 8, s = idx & 255;
    float pm = g_phall[(size_t)r * 512 + s];
    float ps = softplusf_(g_phall[(size_t)r * 512 + 256 + s]) + 0.1f;
    float pr = pm + ps * g_noise[idx];
    if (full) { out[O_PM + idx] = pm; out[O_PS + idx] = ps; out[O_PRI + idx] = pr; }
}

// ---------------- launch ----------------
extern "C" void kernel_launch(void* const* d_in, const int* in_sizes, int n_in,
                              void* d_out, int out_size) {
    const float* actions      = (const float*)d_in[0];
    const float* prev_state   = (const float*)d_in[1];
    const float* prev_belief  = (const float*)d_in[2];
    const float* observations = (const float*)d_in[3];
    const float* nonterminals = (const float*)d_in[4];
    const float* W_sa = (const float*)d_in[5];
    const float* b_sa = (const float*)d_in[6];
    const float* W_x  = (const float*)d_in[7];
    const float* W_h  = (const float*)d_in[8];
    const float* b_x  = (const float*)d_in[9];
    const float* b_h  = (const float*)d_in[10];
    const float* W_bp = (const float*)d_in[11];
    const float* b_bp = (const float*)d_in[12];
    const float* W_sp = (const float*)d_in[13];
    const float* b_sp = (const float*)d_in[14];
    const float* W_bq = (const float*)d_in[15];
    const float* b_bq = (const float*)d_in[16];
    const float* W_sq = (const float*)d_in[17];
    const float* b_sq = (const float*)d_in[18];
    float* out = (float*)d_out;

    const size_t FULL = (size_t)TT * BB * (HH + 6 * SS);
    const int full = (size_t)out_size >= FULL;

    float *qobs, *phall;
    u16 *acth, *actl, *obsh, *obsl, *bah, *bal, *p1h, *p1l;
    u16 *wsa_h, *wsa_l, *wx_h, *wx_l, *wh_h, *wh_l;
    u16 *wbq_h, *wbq_l, *wbqo_h, *wbqo_l, *wsq_h, *wsq_l, *wbp_h, *wbp_l, *wsp_h, *wsp_l;
    cudaGetSymbolAddress((void**)&qobs, g_qobs);
    cudaGetSymbolAddress((void**)&phall, g_phall);
    cudaGetSymbolAddress((void**)&acth, g_acth); cudaGetSymbolAddress((void**)&actl, g_actl);
    cudaGetSymbolAddress((void**)&obsh, g_obsh); cudaGetSymbolAddress((void**)&obsl, g_obsl);
    cudaGetSymbolAddress((void**)&bah, g_bah);   cudaGetSymbolAddress((void**)&bal, g_bal);
    cudaGetSymbolAddress((void**)&p1h, g_p1h);   cudaGetSymbolAddress((void**)&p1l, g_p1l);
    cudaGetSymbolAddress((void**)&wsa_h, g_wsa_h);   cudaGetSymbolAddress((void**)&wsa_l, g_wsa_l);
    cudaGetSymbolAddress((void**)&wx_h, g_wx_h);     cudaGetSymbolAddress((void**)&wx_l, g_wx_l);
    cudaGetSymbolAddress((void**)&wh_h, g_wh_h);     cudaGetSymbolAddress((void**)&wh_l, g_wh_l);
    cudaGetSymbolAddress((void**)&wbq_h, g_wbq_h);   cudaGetSymbolAddress((void**)&wbq_l, g_wbq_l);
    cudaGetSymbolAddress((void**)&wbqo_h, g_wbqo_h); cudaGetSymbolAddress((void**)&wbqo_l, g_wbqo_l);
    cudaGetSymbolAddress((void**)&wsq_h, g_wsq_h);   cudaGetSymbolAddress((void**)&wsq_l, g_wsq_l);
    cudaGetSymbolAddress((void**)&wbp_h, g_wbp_h);   cudaGetSymbolAddress((void**)&wbp_l, g_wbp_l);
    cudaGetSymbolAddress((void**)&wsp_h, g_wsp_h);   cudaGetSymbolAddress((void**)&wsp_l, g_wsp_l);

    cudaFuncSetAttribute(rssm_kernel, cudaFuncAttributeMaxDynamicSharedMemorySize, ENG_SMEM);
    cudaFuncSetAttribute(gemm_big, cudaFuncAttributeMaxDynamicSharedMemorySize, ENG_SMEM);

    noise_kernel<<<(2 * TT * BB * SS + 255) / 256, 256>>>();
    init_kernel<<<(BB * HH + 255) / 256, 256>>>(prev_state, prev_belief, nonterminals);
    split_kernel<<<(TT * BB * AA + 255) / 256, 256>>>(actions, (long long)TT * BB * AA, acth, actl);
    split_kernel<<<(TT * BB * OO + 255) / 256, 256>>>(observations, (long long)TT * BB * OO, obsh, obsl);
    wsplit_kernel<<<(320 * HH + 255) / 256, 256>>>(W_sa, 320, HH, wsa_h, wsa_l);
    wsplit_kernel<<<(HH * 3 * HH + 255) / 256, 256>>>(W_x, HH, 3 * HH, wx_h, wx_l);
    wsplit_kernel<<<(HH * 3 * HH + 255) / 256, 256>>>(W_h, HH, 3 * HH, wh_h, wh_l);
    wsplit_kernel<<<(HH * HH + 255) / 256, 256>>>(W_bq, HH, HH, wbq_h, wbq_l);
    wsplit_kernel<<<(HH * HH + 255) / 256, 256>>>(W_bq + (size_t)HH * HH, HH, HH, wbqo_h, wbqo_l);
    wsplit_kernel<<<(HH * 2 * SS + 255) / 256, 256>>>(W_sq, HH, 2 * SS, wsq_h, wsq_l);
    wsplit_kernel<<<(HH * HH + 255) / 256, 256>>>(W_bp, HH, HH, wbp_h, wbp_l);
    wsplit_kernel<<<(HH * 2 * SS + 255) / 256, 256>>>(W_sp, HH, 2 * SS, wsp_h, wsp_l);

    // Pre: qobs = obs_all @ Wt_bqo   [12800,1024]x[1024,1024]
    {
        BigOp b{obsh, obsl, OO, wbqo_h, wbqo_l, OO, OO,
                nullptr, qobs, HH, nullptr, nullptr, 0, 0};
        gemm_big<<<dim3(HH / 128, (TT * BB) / 128), 256, ENG_SMEM>>>(b);
    }

    // Scan
    rssm_kernel<<<NCTA, 256, ENG_SMEM>>>(nonterminals, b_sa, b_x, b_h, b_bq, b_sq,
                                         out, full);

    // Post: prior branch batched over all T
    {
        BigOp b{bah, bal, HH, wbp_h, wbp_l, HH, HH,
                b_bp, nullptr, 0, p1h, p1l, HH, 1};
        gemm_big<<<dim3(HH / 128, (TT * BB) / 128), 256, ENG_SMEM>>>(b);
    }
    {
        BigOp b{p1h, p1l, HH, wsp_h, wsp_l, HH, HH,
                b_sp, phall, 2 * SS, nullptr, nullptr, 0, 0};
        gemm_big<<<dim3(2 * SS / 128, (TT * BB) / 128), 256, ENG_SMEM>>>(b);
    }
    prior_heads_kernel<<<(TT * BB * SS + 255) / 256, 256>>>(out, full);
}

// round 17
// speedup vs baseline: 1.6861x; 1.1478x over previous
#include <cuda_runtime.h>
#include <cuda_bf16.h>
#include <cstdint>
#include <math.h>

// Problem dims (fixed by setup_inputs)
#define TT 50
#define BB 256
#define AA 64
#define SS 256
#define HH 1024
#define OO 1024
#define NCTA 148
#define BH  (BB * HH)
#define B3H (BB * 3 * HH)
#define B2S (BB * 2 * SS)
#define TBH (TT * BB * HH)

typedef unsigned short u16;
typedef uint32_t u32;

// ---------------- device scratch (static allocation only) ----------------
__device__ float g_noise[2 * TT * BB * SS];
__device__ float g_qobs[TBH];                       // obs @ W_bq[H:]
__device__ float g_phall[TT * BB * 2 * SS];
__device__ float g_belief[BH];
__device__ float g_hg[B3H];
__device__ float g_xg[B3H];
__device__ float g_qh[B2S];
// bf16 hi/lo activation splits
__device__ __align__(128) u16 g_bel_h[BH],  g_bel_l[BH];
__device__ __align__(128) u16 g_st_h[BB*SS], g_st_l[BB*SS];
__device__ __align__(128) u16 g_h1h[BH],  g_h1l[BH];
__device__ __align__(128) u16 g_q1h[BH],  g_q1l[BH];
__device__ __align__(128) u16 g_acth[TT*BB*AA], g_actl[TT*BB*AA];
__device__ __align__(128) u16 g_obsh[TT*BB*OO], g_obsl[TT*BB*OO];
__device__ __align__(128) u16 g_bah[TBH], g_bal[TBH];      // belief_all splits
__device__ __align__(128) u16 g_p1h[TBH], g_p1l[TBH];      // p1_all splits
// transposed bf16 weights [N, K]
__device__ __align__(128) u16 g_wsa_h[HH*320],   g_wsa_l[HH*320];
__device__ __align__(128) u16 g_wx_h[3*HH*HH],   g_wx_l[3*HH*HH];
__device__ __align__(128) u16 g_wh_h[3*HH*HH],   g_wh_l[3*HH*HH];
__device__ __align__(128) u16 g_wbq_h[HH*HH],    g_wbq_l[HH*HH];     // top half
__device__ __align__(128) u16 g_wbqo_h[HH*HH],   g_wbqo_l[HH*HH];    // bottom half
__device__ __align__(128) u16 g_wsq_h[2*SS*HH],  g_wsq_l[2*SS*HH];
__device__ __align__(128) u16 g_wbp_h[HH*HH],    g_wbp_l[HH*HH];
__device__ __align__(128) u16 g_wsp_h[2*SS*HH],  g_wsp_l[2*SS*HH];
__device__ unsigned g_arrive;
__device__ unsigned g_release;
__device__ unsigned g_ticket;

// ---------------- helpers ----------------
__device__ __forceinline__ float sigmoidf_(float x) { return 1.0f / (1.0f + expf(-x)); }
__device__ __forceinline__ float softplusf_(float x) {
    return fmaxf(x, 0.0f) + log1pf(expf(-fabsf(x)));
}
__device__ __forceinline__ unsigned ld_acquire(unsigned* p) {
    unsigned v;
    asm volatile("ld.acquire.gpu.u32 %0, [%1];" : "=r"(v) : "l"(p));
    return v;
}
__device__ __forceinline__ u16 f2bf(float x) {
    __nv_bfloat16 b = __float2bfloat16(x);
    return *reinterpret_cast<u16*>(&b);
}
__device__ __forceinline__ float bf2f(u16 u) {
    __nv_bfloat16 b = *reinterpret_cast<__nv_bfloat16*>(&u);
    return __bfloat162float(b);
}
__device__ __forceinline__ u32 smem_u32(const void* p) {
    u32 a;
    asm("{ .reg .u64 t; cvta.to.shared.u64 t, %1; cvt.u32.u64 %0, t; }"
        : "=r"(a) : "l"(p));
    return a;
}

// ---------------- MMA primitives (baseline PTX, legal at compute_103) ------
__device__ __forceinline__ void ldsm4(u32* r, u32 addr) {
    asm volatile("ldmatrix.sync.aligned.m8n8.x4.shared.b16 {%0,%1,%2,%3}, [%4];"
                 : "=r"(r[0]), "=r"(r[1]), "=r"(r[2]), "=r"(r[3]) : "r"(addr));
}
__device__ __forceinline__ void mma16816(float* c, const u32* a, const u32* b) {
    asm volatile(
        "mma.sync.aligned.m16n8k16.row.col.f32.bf16.bf16.f32 "
        "{%0,%1,%2,%3}, {%4,%5,%6,%7}, {%8,%9}, {%0,%1,%2,%3};"
        : "+f"(c[0]), "+f"(c[1]), "+f"(c[2]), "+f"(c[3])
        : "r"(a[0]), "r"(a[1]), "r"(a[2]), "r"(a[3]), "r"(b[0]), "r"(b[1]));
}

// ---------------- grid-wide barrier + ticket reset ----------------
__device__ __forceinline__ void grid_bar(unsigned gen) {
    __syncthreads();
    if (threadIdx.x == 0) {
        __threadfence();
        if (atomicAdd(&g_arrive, 1) == gridDim.x - 1) {
            g_arrive = 0;
            g_ticket = 0;
            __threadfence();
            atomicExch(&g_release, gen);
        } else {
            while (ld_acquire(&g_release) < gen) __nanosleep(32);
        }
    }
    __syncthreads();
}

// ---------------- JAX threefry2x32 noise (key = (0,42)) ----------------
__device__ __forceinline__ u32 rotl32(u32 x, int r) { return (x << r) | (x >> (32 - r)); }
__device__ __forceinline__ float normal_from_bits(u32 bits) {
    u32 fb = (bits >> 9) | 0x3f800000u;
    float f = __uint_as_float(fb) - 1.0f;
    const float lo = -0.99999994f;
    float u = f * 2.0f + lo;
    u = fmaxf(lo, u);
    float w = -log1pf(-u * u);
    float p;
    if (w < 5.0f) {
        w -= 2.5f;
        p = 2.81022636e-08f;
        p = fmaf(p, w, 3.43273939e-07f);
        p = fmaf(p, w, -3.5233877e-06f);
        p = fmaf(p, w, -4.39150654e-06f);
        p = fmaf(p, w, 0.00021858087f);
        p = fmaf(p, w, -0.00125372503f);
        p = fmaf(p, w, -0.00417768164f);
        p = fmaf(p, w, 0.246640727f);
        p = fmaf(p, w, 1.50140941f);
    } else {
        w = sqrtf(w) - 3.0f;
        p = -0.000200214257f;
        p = fmaf(p, w, 0.000100950558f);
        p = fmaf(p, w, 0.00134934322f);
        p = fmaf(p, w, -0.00367342844f);
        p = fmaf(p, w, 0.00573950773f);
        p = fmaf(p, w, -0.0076224613f);
        p = fmaf(p, w, 0.00943887047f);
        p = fmaf(p, w, 1.00167406f);
        p = fmaf(p, w, 2.83297682f);
    }
    return 1.41421356f * (p * u);
}

__global__ void noise_kernel() {
    const int total = 2 * TT * BB * SS;
    int i = blockIdx.x * blockDim.x + threadIdx.x;
    if (i >= total) return;
    const u32 k0 = 0u, k1 = 42u;
    const u32 k2 = k0 ^ k1 ^ 0x1BD11BDAu;
    u32 x0 = 0u, x1 = (u32)i;
    x0 += k0; x1 += k1;
#define RND(r) { x0 += x1; x1 = rotl32(x1, r); x1 ^= x0; }
    RND(13) RND(15) RND(26) RND(6)   x0 += k1; x1 += k2 + 1u;
    RND(17) RND(29) RND(16) RND(24)  x0 += k2; x1 += k0 + 2u;
    RND(13) RND(15) RND(26) RND(6)   x0 += k0; x1 += k1 + 3u;
    RND(17) RND(29) RND(16) RND(24)  x0 += k1; x1 += k2 + 4u;
    RND(13) RND(15) RND(26) RND(6)   x0 += k2; x1 += k0 + 5u;
#undef RND
    g_noise[i] = normal_from_bits(x0 ^ x1);
}

__global__ void init_kernel(const float* __restrict__ prev_state,
                            const float* __restrict__ prev_belief,
                            const float* __restrict__ nonterminals) {
    int i = blockIdx.x * blockDim.x + threadIdx.x;
    if (i == 0) { g_arrive = 0; g_release = 0; g_ticket = 0; }
    if (i < BB * SS) {
        float sm = prev_state[i] * nonterminals[i >> 8];
        u16 h = f2bf(sm);
        g_st_h[i] = h; g_st_l[i] = f2bf(sm - bf2f(h));
    }
    if (i < BB * HH) {
        float v = prev_belief[i];
        g_belief[i] = v;
        u16 h = f2bf(v);
        g_bel_h[i] = h; g_bel_l[i] = f2bf(v - bf2f(h));
    }
}

// ---------------- fused weight split+transpose: W[K,N] -> Wt[N,K] ----------
#define NSEG 8
struct WSegs {
    const float* W[NSEG];
    u16 *th[NSEG], *tl[NSEG];
    int K[NSEG], N[NSEG];
    long long base[NSEG + 1];
};

__global__ void wsplit_all_kernel(WSegs s) {
    long long i = (long long)blockIdx.x * 256 + threadIdx.x;
    if (i >= s.base[NSEG]) return;
    int seg = 0;
#pragma unroll
    for (int j = 1; j < NSEG; ++j)
        if (i >= s.base[j]) seg = j;
    long long r = i - s.base[seg];
    int K = s.K[seg], N = s.N[seg];
    int n = (int)(r / K), k = (int)(r % K);
    float v = s.W[seg][(size_t)k * N + n];
    u16 h = f2bf(v);
    s.th[seg][r] = h; s.tl[seg][r] = f2bf(v - bf2f(h));
}

__global__ void split_kernel(const float* __restrict__ a, long long n,
                             u16* __restrict__ oh, u16* __restrict__ ol) {
    long long i = (long long)blockIdx.x * 256 + threadIdx.x;
    if (i >= n) return;
    float v = a[i];
    u16 h = f2bf(v);
    oh[i] = h; ol[i] = f2bf(v - bf2f(h));
}

// ---------------- HMMA tile engine ----------------
// smem: 2 buffers x (Ah, Al, Bh, Bl), each 128 rows x 32 bf16 padded to 80B/row.
#define ROWB 80
#define MATB (128 * ROWB)            // 10240
#define BUFB (4 * MATB)              // 40960
#define ENG_SMEM (2 * BUFB)          // 81920
#define OF_AH 0
#define OF_AL MATB
#define OF_BH (2 * MATB)
#define OF_BL (3 * MATB)

struct MOp {
    const u16 *ah, *al; int lda; int k0;    // A block0 (pre-offset to tile m0)
    const u16 *a1h, *a1l; int lda1;         // concat block (k >= k0)
    const u16 *bh, *bl; int ldb;            // B = Wt rows (pre-offset n0)
    int K;                                  // multiple of 32
    int mrows;                              // 128 or 64
    const float* bias;                      // pre-offset n0 (or null)
    const float* add; int ldadd;            // pre-offset (or null)
    float* outf; int ldout;                 // pre-offset (or null)
    u16 *oh, *ol; int ldoh;                 // pre-offset (or null)
    int relu;
};

__device__ void mma_tile(const MOp op, char* sm, u32 su) {
    const int tid = threadIdx.x;
    const int lane = tid & 31;
    const int wid = tid >> 5;
    const int nch = op.K >> 5;

    const bool m128 = (op.mrows == 128);
    const int wm = m128 ? (wid & 1) * 64 : 0;
    const int wnb = m128 ? (wid >> 1) * 32 : wid * 16;
    const int na = m128 ? 4 : 2;

    // staging ids
    const int arow = tid >> 1;
    const int half = tid & 1;
    const bool doA = arow < op.mrows;

    float acc[4][4][4];
#pragma unroll
    for (int i = 0; i < 4; ++i)
#pragma unroll
        for (int j = 0; j < 4; ++j)
#pragma unroll
            for (int k = 0; k < 4; ++k) acc[i][j][k] = 0.0f;

    uint4 pah[2], pal[2], pbh[2], pbl[2];
    auto load_regs = [&](int c) {
        int kc = c << 5;
        if (doA) {
            const u16 *sh, *sl; int ld;
            if (kc < op.k0) { sh = op.ah + kc; sl = op.al + kc; ld = op.lda; }
            else { sh = op.a1h + (kc - op.k0); sl = op.a1l + (kc - op.k0); ld = op.lda1; }
            const uint4* ph = (const uint4*)(sh + (size_t)arow * ld + half * 16);
            const uint4* pl = (const uint4*)(sl + (size_t)arow * ld + half * 16);
            pah[0] = ph[0]; pah[1] = ph[1];
            pal[0] = pl[0]; pal[1] = pl[1];
        }
        const uint4* qh = (const uint4*)(op.bh + (size_t)arow * op.ldb + kc + half * 16);
        const uint4* ql = (const uint4*)(op.bl + (size_t)arow * op.ldb + kc + half * 16);
        pbh[0] = qh[0]; pbh[1] = qh[1];
        pbl[0] = ql[0]; pbl[1] = ql[1];
    };
    auto sts = [&](int b) {
        char* base = sm + b * BUFB;
        int off = arow * ROWB + half * 32;
        if (doA) {
            *(uint4*)(base + OF_AH + off) = pah[0];
            *(uint4*)(base + OF_AH + off + 16) = pah[1];
            *(uint4*)(base + OF_AL + off) = pal[0];
            *(uint4*)(base + OF_AL + off + 16) = pal[1];
        }
        *(uint4*)(base + OF_BH + off) = pbh[0];
        *(uint4*)(base + OF_BH + off + 16) = pbh[1];
        *(uint4*)(base + OF_BL + off) = pbl[0];
        *(uint4*)(base + OF_BL + off + 16) = pbl[1];
    };

    // fragment address components
    const int a_row0 = wm + (lane & 7) + ((lane >> 3) & 1) * 8;
    const int a_kb0  = ((lane >> 4) & 1) * 16;
    const int b_row0 = wnb + (lane & 7) + ((lane >> 4) & 1) * 8;
    const int b_kb0  = ((lane >> 3) & 1) * 16;

    __syncthreads();
    load_regs(0);
    sts(0);
    __syncthreads();

    int buf = 0;
    for (int c = 0; c < nch; ++c) {
        const bool hn = (c + 1 < nch);
        if (hn) load_regs(c + 1);
        u32 bb = su + buf * BUFB;
#pragma unroll
        for (int ks = 0; ks < 2; ++ks) {
            u32 ah[4][4], al[4][4], bh[4][2], bl[4][2];
#pragma unroll
            for (int am = 0; am < 4; ++am) {
                u32 ra = bb + OF_AH + (u32)(a_row0 + am * 16) * ROWB + ks * 32 + a_kb0;
                ldsm4(ah[am], ra);
                ldsm4(al[am], ra + (OF_AL - OF_AH));
            }
#pragma unroll
            for (int p = 0; p < 2; ++p) {
                if (p * 2 >= na) break;
                u32 rb = bb + OF_BH + (u32)(b_row0 + p * 16) * ROWB + ks * 32 + b_kb0;
                u32 t[4];
                ldsm4(t, rb);
                bh[2 * p][0] = t[0]; bh[2 * p][1] = t[1];
                bh[2 * p + 1][0] = t[2]; bh[2 * p + 1][1] = t[3];
                ldsm4(t, rb + (OF_BL - OF_BH));
                bl[2 * p][0] = t[0]; bl[2 * p][1] = t[1];
                bl[2 * p + 1][0] = t[2]; bl[2 * p + 1][1] = t[3];
            }
#pragma unroll
            for (int am = 0; am < 4; ++am)
#pragma unroll
                for (int an = 0; an < 4; ++an) {
                    if (an >= na) break;
                    mma16816(acc[am][an], ah[am], bh[an]);
                    mma16816(acc[am][an], ah[am], bl[an]);
                    mma16816(acc[am][an], al[am], bh[an]);
                }
        }
        if (hn) {
            sts(buf ^ 1);
            __syncthreads();
            buf ^= 1;
        }
    }

    // epilogue
    auto emit = [&](int row, int col, float v0, float v1) {
        if (op.bias) { v0 += op.bias[col]; v1 += op.bias[col + 1]; }
        if (op.add) {
            const float* ar = op.add + (size_t)row * op.ldadd + col;
            v0 += ar[0]; v1 += ar[1];
        }
        if (op.relu) { v0 = fmaxf(v0, 0.0f); v1 = fmaxf(v1, 0.0f); }
        if (op.outf) {
            *(float2*)(op.outf + (size_t)row * op.ldout + col) = make_float2(v0, v1);
        }
        if (op.oh) {
            u16 h0 = f2bf(v0), h1 = f2bf(v1);
            ushort2 hh = make_ushort2(h0, h1);
            ushort2 ll = make_ushort2(f2bf(v0 - bf2f(h0)), f2bf(v1 - bf2f(h1)));
            *(ushort2*)(op.oh + (size_t)row * op.ldoh + col) = hh;
            *(ushort2*)(op.ol + (size_t)row * op.ldoh + col) = ll;
        }
    };
#pragma unroll
    for (int am = 0; am < 4; ++am)
#pragma unroll
        for (int an = 0; an < 4; ++an) {
            if (an >= na) break;
            int col = wnb + an * 8 + ((lane & 3) << 1);
            int row = wm + am * 16 + (lane >> 2);
            emit(row, col, acc[am][an][0], acc[am][an][1]);
            emit(row + 8, col, acc[am][an][2], acc[am][an][3]);
        }
    __syncthreads();
}

// ---------------- static-grid big GEMM ----------------
struct BigOp {
    const u16 *ah, *al; int lda;
    const u16 *bh, *bl; int ldb;
    int K;
    const float* bias;
    float* outf; int ldout;
    u16 *oh, *ol; int ldoh;
    int relu;
};

__global__ __launch_bounds__(256, 1) void gemm_big(BigOp b) {
    extern __shared__ __align__(128) char smem[];
    int m0 = blockIdx.y * 128, n0 = blockIdx.x * 128;
    MOp op{};
    op.ah = b.ah + (size_t)m0 * b.lda; op.al = b.al + (size_t)m0 * b.lda;
    op.lda = b.lda; op.k0 = b.K;
    op.bh = b.bh + (size_t)n0 * b.ldb; op.bl = b.bl + (size_t)n0 * b.ldb;
    op.ldb = b.ldb; op.K = b.K; op.mrows = 128;
    op.bias = b.bias ? b.bias + n0 : nullptr;
    if (b.outf) { op.outf = b.outf + (size_t)m0 * b.ldout + n0; op.ldout = b.ldout; }
    if (b.oh) {
        op.oh = b.oh + (size_t)m0 * b.ldoh + n0;
        op.ol = b.ol + (size_t)m0 * b.ldoh + n0; op.ldoh = b.ldoh;
    }
    op.relu = b.relu;
    mma_tile(op, smem, smem_u32(smem));
}

// ---------------- persistent scan kernel ----------------
__global__ __launch_bounds__(256, 1) void rssm_kernel(
    const float* __restrict__ nonterminals,
    const float* __restrict__ b_sa,
    const float* __restrict__ b_x,  const float* __restrict__ b_h,
    const float* __restrict__ b_bq, const float* __restrict__ b_sq,
    float* __restrict__ out, int full)
{
    extern __shared__ __align__(128) char smem[];
    __shared__ unsigned sPiece;
    const int bid = blockIdx.x;
    const int stride = gridDim.x;
    const int tid = threadIdx.x;
    unsigned gen = 0;
    u32 su = smem_u32(smem);

    const size_t O_BEL  = 0;
    const size_t O_POST = (size_t)TT * BB * HH + 3 * (size_t)TT * BB * SS;
    const size_t O_QM   = O_POST + (size_t)TT * BB * SS;
    const size_t O_QS   = O_QM   + (size_t)TT * BB * SS;

    auto grab = [&]() -> unsigned {
        __syncthreads();
        if (tid == 0) sPiece = atomicAdd(&g_ticket, 1);
        __syncthreads();
        return sPiece;
    };

    for (int t = 0; t < TT; ++t) {
        // Phase A: h1 (32 tiles 64x128) + hg (96 tiles 64x128)
        for (unsigned p = grab(); p < 128; p = grab()) {
            MOp op{};
            if (p < 32) {
                int m0 = (int)(p & 3) * 64, n0 = (int)(p >> 2) * 128;
                op.ah = g_st_h + (size_t)m0 * SS; op.al = g_st_l + (size_t)m0 * SS;
                op.lda = SS; op.k0 = 256;
                op.a1h = g_acth + (size_t)t * BB * AA + (size_t)m0 * AA;
                op.a1l = g_actl + (size_t)t * BB * AA + (size_t)m0 * AA;
                op.lda1 = AA;
                op.bh = g_wsa_h + (size_t)n0 * 320; op.bl = g_wsa_l + (size_t)n0 * 320;
                op.ldb = 320; op.K = 320; op.mrows = 64;
                op.bias = b_sa + n0; op.relu = 1;
                op.oh = g_h1h + (size_t)m0 * HH + n0;
                op.ol = g_h1l + (size_t)m0 * HH + n0; op.ldoh = HH;
            } else {
                unsigned q = p - 32;
                int m0 = (int)(q & 3) * 64, n0 = (int)(q >> 2) * 128;
                op.ah = g_bel_h + (size_t)m0 * HH; op.al = g_bel_l + (size_t)m0 * HH;
                op.lda = HH; op.k0 = HH; op.K = HH; op.mrows = 64;
                op.bh = g_wh_h + (size_t)n0 * HH; op.bl = g_wh_l + (size_t)n0 * HH;
                op.ldb = HH;
                op.outf = g_hg + (size_t)m0 * 3 * HH + n0; op.ldout = 3 * HH;
            }
            mma_tile(op, smem, su);
        }
        grid_bar(++gen);

        // Phase B: xg (96 tiles 64x128)
        for (unsigned p = grab(); p < 96; p = grab()) {
            int m0 = (int)(p & 3) * 64, n0 = (int)(p >> 2) * 128;
            MOp op{};
            op.ah = g_h1h + (size_t)m0 * HH; op.al = g_h1l + (size_t)m0 * HH;
            op.lda = HH; op.k0 = HH; op.K = HH; op.mrows = 64;
            op.bh = g_wx_h + (size_t)n0 * HH; op.bl = g_wx_l + (size_t)n0 * HH;
            op.ldb = HH;
            op.outf = g_xg + (size_t)m0 * 3 * HH + n0; op.ldout = 3 * HH;
            mma_tile(op, smem, su);
        }
        grid_bar(++gen);

        // Phase C: GRU elementwise -> belief (+ output + hi/lo + belief_all split)
        {
            float* ob = out + O_BEL + (size_t)t * BB * HH;
            u16* bah = g_bah + (size_t)t * BH;
            u16* bal = g_bal + (size_t)t * BH;
            for (int idx = bid * 256 + tid; idx < BB * HH; idx += stride * 256) {
                int b = idx >> 10, j = idx & 1023;
                size_t base = (size_t)b * 3072 + j;
                float xz = g_xg[base] + b_x[j];
                float xr = g_xg[base + 1024] + b_x[1024 + j];
                float xh = g_xg[base + 2048] + b_x[2048 + j];
                float hz = g_hg[base] + b_h[j];
                float hr = g_hg[base + 1024] + b_h[1024 + j];
                float hh = g_hg[base + 2048] + b_h[2048 + j];
                float z = sigmoidf_(xz + hz);
                float r = sigmoidf_(xr + hr);
                float cand = tanhf(xh + r * hh);
                float bo = g_belief[idx];
                float bn = z * bo + (1.0f - z) * cand;
                g_belief[idx] = bn;
                ob[idx] = bn;
                u16 h = f2bf(bn);
                u16 l = f2bf(bn - bf2f(h));
                g_bel_h[idx] = h; g_bel_l[idx] = l;
                bah[idx] = h; bal[idx] = l;
            }
        }
        grid_bar(++gen);

        // Phase D: q1 = relu(bel @ W_bq_top + qobs + b_bq) (32 tiles 64x128)
        for (unsigned p = grab(); p < 32; p = grab()) {
            int m0 = (int)(p & 3) * 64, n0 = (int)(p >> 2) * 128;
            MOp op{};
            op.ah = g_bel_h + (size_t)m0 * HH; op.al = g_bel_l + (size_t)m0 * HH;
            op.lda = HH; op.k0 = HH; op.K = HH; op.mrows = 64;
            op.bh = g_wbq_h + (size_t)n0 * HH; op.bl = g_wbq_l + (size_t)n0 * HH;
            op.ldb = HH;
            op.bias = b_bq + n0;
            op.add = g_qobs + (size_t)t * BH + (size_t)m0 * HH + n0; op.ldadd = HH;
            op.relu = 1;
            op.oh = g_q1h + (size_t)m0 * HH + n0;
            op.ol = g_q1l + (size_t)m0 * HH + n0; op.ldoh = HH;
            mma_tile(op, smem, su);
        }
        grid_bar(++gen);

        // Phase E: qh = q1 @ W_sq (16 tiles 64x128)
        for (unsigned p = grab(); p < 16; p = grab()) {
            int m0 = (int)(p & 3) * 64, n0 = (int)(p >> 2) * 128;
            MOp op{};
            op.ah = g_q1h + (size_t)m0 * HH; op.al = g_q1l + (size_t)m0 * HH;
            op.lda = HH; op.k0 = HH; op.K = HH; op.mrows = 64;
            op.bh = g_wsq_h + (size_t)n0 * HH; op.bl = g_wsq_l + (size_t)n0 * HH;
            op.ldb = HH;
            op.outf = g_qh + (size_t)m0 * 2 * SS + n0; op.ldout = 2 * SS;
            mma_tile(op, smem, su);
        }
        grid_bar(++gen);

        // Phase F: posterior heads -> outputs + next state
        {
            const float* nQ = g_noise + (size_t)(TT + t) * BB * SS;
            for (int idx = bid * 256 + tid; idx < BB * SS; idx += stride * 256) {
                int b = idx >> 8, s = idx & 255;
                float qm = g_qh[b * 512 + s] + b_sq[s];
                float qs = softplusf_(g_qh[b * 512 + 256 + s] + b_sq[256 + s]) + 0.1f;
                float po = qm + qs * nQ[idx];
                if (full) {
                    size_t o = (size_t)t * BB * SS + idx;
                    out[O_QM + o] = qm; out[O_QS + o] = qs; out[O_POST + o] = po;
                }
                if (t + 1 < TT) {
                    float sm = po * nonterminals[(size_t)(t + 1) * BB + b];
                    u16 h = f2bf(sm);
                    g_st_h[idx] = h; g_st_l[idx] = f2bf(sm - bf2f(h));
                }
            }
        }
        grid_bar(++gen);
    }
}

// ---------------- prior heads elementwise (post-pass) ----------------
__global__ void prior_heads_kernel(float* __restrict__ out, int full) {
    const size_t O_PRI = (size_t)TT * BB * HH;
    const size_t O_PM  = O_PRI + (size_t)TT * BB * SS;
    const size_t O_PS  = O_PM  + (size_t)TT * BB * SS;
    int idx = blockIdx.x * blockDim.x + threadIdx.x;
    if (idx >= TT * BB * SS) return;
    int r = idx >> 8, s = idx & 255;
    float pm = g_phall[(size_t)r * 512 + s];
    float ps = softplusf_(g_phall[(size_t)r * 512 + 256 + s]) + 0.1f;
    float pr = pm + ps * g_noise[idx];
    if (full) { out[O_PM + idx] = pm; out[O_PS + idx] = ps; out[O_PRI + idx] = pr; }
}

// ---------------- launch ----------------
extern "C" void kernel_launch(void* const* d_in, const int* in_sizes, int n_in,
                              void* d_out, int out_size) {
    const float* actions      = (const float*)d_in[0];
    const float* prev_state   = (const float*)d_in[1];
    const float* prev_belief  = (const float*)d_in[2];
    const float* observations = (const float*)d_in[3];
    const float* nonterminals = (const float*)d_in[4];
    const float* W_sa = (const float*)d_in[5];
    const float* b_sa = (const float*)d_in[6];
    const float* W_x  = (const float*)d_in[7];
    const float* W_h  = (const float*)d_in[8];
    const float* b_x  = (const float*)d_in[9];
    const float* b_h  = (const float*)d_in[10];
    const float* W_bp = (const float*)d_in[11];
    const float* b_bp = (const float*)d_in[12];
    const float* W_sp = (const float*)d_in[13];
    const float* b_sp = (const float*)d_in[14];
    const float* W_bq = (const float*)d_in[15];
    const float* b_bq = (const float*)d_in[16];
    const float* W_sq = (const float*)d_in[17];
    const float* b_sq = (const float*)d_in[18];
    float* out = (float*)d_out;

    const size_t FULL = (size_t)TT * BB * (HH + 6 * SS);
    const int full = (size_t)out_size >= FULL;

    float *qobs, *phall;
    u16 *acth, *actl, *obsh, *obsl, *bah, *bal, *p1h, *p1l;
    u16 *wsa_h, *wsa_l, *wx_h, *wx_l, *wh_h, *wh_l;
    u16 *wbq_h, *wbq_l, *wbqo_h, *wbqo_l, *wsq_h, *wsq_l, *wbp_h, *wbp_l, *wsp_h, *wsp_l;
    cudaGetSymbolAddress((void**)&qobs, g_qobs);
    cudaGetSymbolAddress((void**)&phall, g_phall);
    cudaGetSymbolAddress((void**)&acth, g_acth); cudaGetSymbolAddress((void**)&actl, g_actl);
    cudaGetSymbolAddress((void**)&obsh, g_obsh); cudaGetSymbolAddress((void**)&obsl, g_obsl);
    cudaGetSymbolAddress((void**)&bah, g_bah);   cudaGetSymbolAddress((void**)&bal, g_bal);
    cudaGetSymbolAddress((void**)&p1h, g_p1h);   cudaGetSymbolAddress((void**)&p1l, g_p1l);
    cudaGetSymbolAddress((void**)&wsa_h, g_wsa_h);   cudaGetSymbolAddress((void**)&wsa_l, g_wsa_l);
    cudaGetSymbolAddress((void**)&wx_h, g_wx_h);     cudaGetSymbolAddress((void**)&wx_l, g_wx_l);
    cudaGetSymbolAddress((void**)&wh_h, g_wh_h);     cudaGetSymbolAddress((void**)&wh_l, g_wh_l);
    cudaGetSymbolAddress((void**)&wbq_h, g_wbq_h);   cudaGetSymbolAddress((void**)&wbq_l, g_wbq_l);
    cudaGetSymbolAddress((void**)&wbqo_h, g_wbqo_h); cudaGetSymbolAddress((void**)&wbqo_l, g_wbqo_l);
    cudaGetSymbolAddress((void**)&wsq_h, g_wsq_h);   cudaGetSymbolAddress((void**)&wsq_l, g_wsq_l);
    cudaGetSymbolAddress((void**)&wbp_h, g_wbp_h);   cudaGetSymbolAddress((void**)&wbp_l, g_wbp_l);
    cudaGetSymbolAddress((void**)&wsp_h, g_wsp_h);   cudaGetSymbolAddress((void**)&wsp_l, g_wsp_l);

    cudaFuncSetAttribute(rssm_kernel, cudaFuncAttributeMaxDynamicSharedMemorySize, ENG_SMEM);
    cudaFuncSetAttribute(gemm_big, cudaFuncAttributeMaxDynamicSharedMemorySize, ENG_SMEM);

    noise_kernel<<<(2 * TT * BB * SS + 255) / 256, 256>>>();
    init_kernel<<<(BB * HH + 255) / 256, 256>>>(prev_state, prev_belief, nonterminals);
    split_kernel<<<(TT * BB * AA + 255) / 256, 256>>>(actions, (long long)TT * BB * AA, acth, actl);
    split_kernel<<<(TT * BB * OO + 255) / 256, 256>>>(observations, (long long)TT * BB * OO, obsh, obsl);

    // fused weight split+transpose (one launch for all 8 weight matrices)
    {
        WSegs s{};
        const float* Ws[NSEG] = {W_sa, W_x, W_h, W_bq, W_bq + (size_t)HH * HH,
                                 W_sq, W_bp, W_sp};
        u16* ths[NSEG] = {wsa_h, wx_h, wh_h, wbq_h, wbqo_h, wsq_h, wbp_h, wsp_h};
        u16* tls[NSEG] = {wsa_l, wx_l, wh_l, wbq_l, wbqo_l, wsq_l, wbp_l, wsp_l};
        int Ks[NSEG] = {320, HH, HH, HH, HH, HH, HH, HH};
        int Ns[NSEG] = {HH, 3 * HH, 3 * HH, HH, HH, 2 * SS, HH, 2 * SS};
        long long acc = 0;
        for (int i = 0; i < NSEG; ++i) {
            s.W[i] = Ws[i]; s.th[i] = ths[i]; s.tl[i] = tls[i];
            s.K[i] = Ks[i]; s.N[i] = Ns[i];
            s.base[i] = acc;
            acc += (long long)Ks[i] * Ns[i];
        }
        s.base[NSEG] = acc;
        wsplit_all_kernel<<<(unsigned)((acc + 255) / 256), 256>>>(s);
    }

    // Pre: qobs = obs_all @ Wt_bqo   [12800,1024]x[1024,1024]
    {
        BigOp b{obsh, obsl, OO, wbqo_h, wbqo_l, OO, OO,
                nullptr, qobs, HH, nullptr, nullptr, 0, 0};
        gemm_big<<<dim3(HH / 128, (TT * BB) / 128), 256, ENG_SMEM>>>(b);
    }

    // Scan
    rssm_kernel<<<NCTA, 256, ENG_SMEM>>>(nonterminals, b_sa, b_x, b_h, b_bq, b_sq,
                                         out, full);

    // Post: prior branch batched over all T
    {
        BigOp b{bah, bal, HH, wbp_h, wbp_l, HH, HH,
                b_bp, nullptr, 0, p1h, p1l, HH, 1};
        gemm_big<<<dim3(HH / 128, (TT * BB) / 128), 256, ENG_SMEM>>>(b);
    }
    {
        BigOp b{p1h, p1l, HH, wsp_h, wsp_l, HH, HH,
                b_sp, phall, 2 * SS, nullptr, nullptr, 0, 0};
        gemm_big<<<dim3(2 * SS / 128, (TT * BB) / 128), 256, ENG_SMEM>>>(b);
    }
    prior_heads_kernel<<<(TT * BB * SS + 255) / 256, 256>>>(out, full);
}